// round 10
// baseline (speedup 1.0000x reference)
#include <cuda_runtime.h>
#include <cuda_fp16.h>
#include <cstdint>

#define SEQ_L 50
#define DIM 100
#define KPAD 128
#define FFDIM 2048
#define KPRED 100
#define EPS 1e-5f
#define BMAX 16384

typedef __half fp16;

// ---------------- scratch (device globals) ---------------------------------
__device__ float g_x  [BMAX * DIM];                   // embedding sums (residual)
__device__ float g_x1 [BMAX * KPAD];                  // LN1 out fp32 (residual)
__device__ float g_ff [BMAX * DIM];
__device__ float g_c  [KPAD];
__device__ fp16  g_Mf  [KPAD * KPAD];                 // attn matrix fp16
__device__ fp16  g_recf[KPAD * KPAD];                 // rec_emb fp16
__device__ fp16  g_x1f[BMAX * KPAD];                  // LN1 out fp16 (MMA operand)
__device__ fp16  g_w1f[FFDIM * KPAD];
__device__ fp16  g_hf [(size_t)BMAX * FFDIM];         // hidden fp16
__device__ fp16  g_w2f[KPAD * FFDIM];

// ---------------- helpers ----------------------------------------------------
__device__ __forceinline__ uint32_t smem_u32(const void* p) {
    uint32_t a;
    asm("{ .reg .u64 t; cvta.to.shared.u64 t, %1; cvt.u32.u64 %0, t; }" : "=r"(a) : "l"(p));
    return a;
}
__device__ __forceinline__ void ldsm_x4(uint32_t addr, uint32_t& r0, uint32_t& r1,
                                        uint32_t& r2, uint32_t& r3) {
    asm volatile("ldmatrix.sync.aligned.m8n8.x4.shared.b16 {%0,%1,%2,%3}, [%4];"
                 : "=r"(r0), "=r"(r1), "=r"(r2), "=r"(r3) : "r"(addr));
}
__device__ __forceinline__ void mma_f16(float* d, const uint32_t* a, const uint32_t* b) {
    asm volatile("mma.sync.aligned.m16n8k16.row.col.f32.f16.f16.f32 "
                 "{%0,%1,%2,%3}, {%4,%5,%6,%7}, {%8,%9}, {%0,%1,%2,%3};"
                 : "+f"(d[0]), "+f"(d[1]), "+f"(d[2]), "+f"(d[3])
                 : "r"(a[0]), "r"(a[1]), "r"(a[2]), "r"(a[3]), "r"(b[0]), "r"(b[1]));
}
__device__ __forceinline__ void cp16(uint32_t saddr, const void* g) {
    asm volatile("cp.async.cg.shared.global [%0], [%1], 16;" :: "r"(saddr), "l"(g));
}
#define CP_COMMIT() asm volatile("cp.async.commit_group;" ::: "memory")
template<int N> __device__ __forceinline__ void cp_wait() {
    asm volatile("cp.async.wait_group %0;" :: "n"(N) : "memory");
}

// 128x128 warp-tiled MMA phase (8 warps, warp tile 32x64)
template<int AS, int NKS>
__device__ __forceinline__ void mma_tile1(uint32_t sb, uint32_t oA, uint32_t oB,
                                          float acc[2][8][4], int wid, int lid) {
    int wm = wid >> 1, wn = wid & 1;
    int arow = wm * 32, brow = wn * 64;
    int lr = lid & 15, lc8 = (lid >> 4) << 3;
    #pragma unroll
    for (int ks = 0; ks < NKS; ks++) {
        int k0 = ks * 16;
        uint32_t a[2][4];
        #pragma unroll
        for (int mi = 0; mi < 2; mi++) {
            uint32_t off = (uint32_t)(((arow + mi * 16 + lr) * AS + k0 + lc8) * 2);
            ldsm_x4(sb + oA + off, a[mi][0], a[mi][1], a[mi][2], a[mi][3]);
        }
        uint32_t b[8][2];
        #pragma unroll
        for (int nj = 0; nj < 4; nj++) {
            uint32_t off = (uint32_t)(((brow + nj * 16 + lr) * AS + k0 + lc8) * 2);
            uint32_t r0, r1, r2, r3;
            ldsm_x4(sb + oB + off, r0, r1, r2, r3);
            b[nj * 2][0] = r0; b[nj * 2 + 1][0] = r1;
            b[nj * 2][1] = r2; b[nj * 2 + 1][1] = r3;
        }
        #pragma unroll
        for (int mi = 0; mi < 2; mi++)
            #pragma unroll
            for (int n = 0; n < 8; n++)
                mma_f16(acc[mi][n], a[mi], b[n]);
    }
}

// 64x128 warp-tiled MMA phase (8 warps, warp tile 32x32) — for gemm2
template<int AS, int NKS>
__device__ __forceinline__ void mma_tile64(uint32_t sb, uint32_t oA, uint32_t oB,
                                           float acc[2][4][4], int wid, int lid) {
    int wm = wid >> 2, wn = wid & 3;
    int arow = wm * 32, brow = wn * 32;
    int lr = lid & 15, lc8 = (lid >> 4) << 3;
    #pragma unroll
    for (int ks = 0; ks < NKS; ks++) {
        int k0 = ks * 16;
        uint32_t a[2][4];
        #pragma unroll
        for (int mi = 0; mi < 2; mi++) {
            uint32_t off = (uint32_t)(((arow + mi * 16 + lr) * AS + k0 + lc8) * 2);
            ldsm_x4(sb + oA + off, a[mi][0], a[mi][1], a[mi][2], a[mi][3]);
        }
        uint32_t b[4][2];
        #pragma unroll
        for (int nj = 0; nj < 2; nj++) {
            uint32_t off = (uint32_t)(((brow + nj * 16 + lr) * AS + k0 + lc8) * 2);
            uint32_t r0, r1, r2, r3;
            ldsm_x4(sb + oB + off, r0, r1, r2, r3);
            b[nj * 2][0] = r0; b[nj * 2 + 1][0] = r1;
            b[nj * 2][1] = r2; b[nj * 2 + 1][1] = r3;
        }
        #pragma unroll
        for (int mi = 0; mi < 2; mi++)
            #pragma unroll
            for (int n = 0; n < 4; n++)
                mma_f16(acc[mi][n], a[mi], b[n]);
    }
}

// ---------------- K0: fused prep ---------------------------------------------
__global__ void prep_all(const float* __restrict__ in_proj_w,
                         const float* __restrict__ in_proj_b,
                         const float* __restrict__ out_proj_w,
                         const float* __restrict__ out_proj_b,
                         const float* __restrict__ rec_emb,
                         const float* __restrict__ w1,
                         const float* __restrict__ w2) {
    int bid = blockIdx.x, tid = threadIdx.x;
    if (bid < 64) {
        int i = bid * 2 + (tid >> 7);
        int j = tid & 127;
        const float* Wv = in_proj_w + 2 * DIM * DIM;
        const float* bv = in_proj_b + 2 * DIM;
        float mv = 0.f;
        if (i < DIM && j < DIM) {
            #pragma unroll 4
            for (int k = 0; k < DIM; k++)
                mv += out_proj_w[i * DIM + k] * Wv[k * DIM + j];
        }
        g_Mf[i * KPAD + j] = __float2half_rn(mv);
        if (j == 0) {
            float s = 0.f;
            if (i < DIM) {
                s = out_proj_b[i];
                for (int k = 0; k < DIM; k++)
                    s += out_proj_w[i * DIM + k] * bv[k];
            }
            g_c[i] = s;
        }
    } else if (bid < 128) {
        int idx = (bid - 64) * 256 + tid;
        int n = idx >> 7, k = idx & 127;
        float v = (n < DIM && k < DIM) ? rec_emb[n * DIM + k] : 0.f;
        g_recf[idx] = __float2half_rn(v);
    } else if (bid < 128 + 1024) {
        int idx = (bid - 128) * 256 + tid;
        int n = idx >> 7, k = idx & 127;
        float v = (k < DIM) ? w1[n * DIM + k] : 0.f;
        g_w1f[idx] = __float2half_rn(v);
    } else {
        int idx = (bid - 1152) * 256 + tid;
        int n = idx >> 11, k = idx & 2047;
        float v = (n < DIM) ? w2[n * FFDIM + k] : 0.f;
        g_w2f[idx] = __float2half_rn(v);
    }
}

// ---------------- fused-tile smem layout (attn_ln1 / ln2_score) -------------
#define FAS 136
#define PL_SZ (128 * FAS * 2)          // 34816
#define F_A  0
#define F_B  PL_SZ
#define F_T  (2 * PL_SZ)
#define F_SMEM (2 * PL_SZ + 512)       // 70144 -> occ 2

// ---------------- K1: fused embed + attn + LN1 --------------------------------
__global__ __launch_bounds__(256, 2)
void attn_ln1_tc(const int* __restrict__ seq, const float* __restrict__ emb,
                 const float* __restrict__ ln1_g, const float* __restrict__ ln1_b) {
    extern __shared__ char smem[];
    uint32_t sb = smem_u32(smem);
    int tid = threadIdx.x, wid = tid >> 5, lid = tid & 31;
    int m0 = blockIdx.x * 128;
    float* cvec = (float*)(smem + F_T);
    if (tid < KPAD) cvec[tid] = g_c[tid];

    // B plane (g_Mf)
    const uint4* B4 = (const uint4*)g_Mf;
    #pragma unroll
    for (int i = 0; i < 8; i++) {
        int idx = tid + i * 256;
        int r = idx >> 4, c = idx & 15;
        uint32_t so = (uint32_t)((r * FAS + c * 8) * 2);
        *(uint4*)(smem + F_B + so) = B4[r * 16 + c];
    }

    // gather-sum: warp wid handles rows [wid*16, wid*16+16), 2 rows in flight
    fp16* Ap = (fp16*)(smem + F_A);
    for (int j = 0; j < 8; j++) {
        int r0 = wid * 16 + j * 2;
        int b0 = m0 + r0, b1 = b0 + 1;
        int i0a = seq[b0 * SEQ_L + lid];
        int i0b = (lid < SEQ_L - 32) ? seq[b0 * SEQ_L + 32 + lid] : 0;
        int i1a = seq[b1 * SEQ_L + lid];
        int i1b = (lid < SEQ_L - 32) ? seq[b1 * SEQ_L + 32 + lid] : 0;
        float a0 = 0.f, a1 = 0.f, a2 = 0.f, a3 = 0.f;
        float d0 = 0.f, d1 = 0.f, d2 = 0.f, d3 = 0.f;
        #pragma unroll 5
        for (int l = 0; l < SEQ_L; l++) {
            int ia = (l < 32) ? __shfl_sync(0xffffffffu, i0a, l)
                              : __shfl_sync(0xffffffffu, i0b, l - 32);
            int ib = (l < 32) ? __shfl_sync(0xffffffffu, i1a, l)
                              : __shfl_sync(0xffffffffu, i1b, l - 32);
            const float* rA = emb + (size_t)ia * DIM;
            const float* rB = emb + (size_t)ib * DIM;
            a0 += rA[lid]; a1 += rA[lid + 32]; a2 += rA[lid + 64];
            d0 += rB[lid]; d1 += rB[lid + 32]; d2 += rB[lid + 64];
            if (lid < 4) { a3 += rA[lid + 96]; d3 += rB[lid + 96]; }
        }
        // fp32 residual
        g_x[(size_t)b0 * DIM + lid]      = a0;
        g_x[(size_t)b0 * DIM + lid + 32] = a1;
        g_x[(size_t)b0 * DIM + lid + 64] = a2;
        if (lid < 4) g_x[(size_t)b0 * DIM + lid + 96] = a3;
        g_x[(size_t)b1 * DIM + lid]      = d0;
        g_x[(size_t)b1 * DIM + lid + 32] = d1;
        g_x[(size_t)b1 * DIM + lid + 64] = d2;
        if (lid < 4) g_x[(size_t)b1 * DIM + lid + 96] = d3;
        // fp16 A plane (dims 100..127 zero via a3/d3=0 for lid>=4)
        Ap[r0 * FAS + lid]            = __float2half_rn(a0);
        Ap[r0 * FAS + lid + 32]       = __float2half_rn(a1);
        Ap[r0 * FAS + lid + 64]       = __float2half_rn(a2);
        Ap[r0 * FAS + lid + 96]       = __float2half_rn((lid < 4) ? a3 : 0.f);
        Ap[(r0 + 1) * FAS + lid]      = __float2half_rn(d0);
        Ap[(r0 + 1) * FAS + lid + 32] = __float2half_rn(d1);
        Ap[(r0 + 1) * FAS + lid + 64] = __float2half_rn(d2);
        Ap[(r0 + 1) * FAS + lid + 96] = __float2half_rn((lid < 4) ? d3 : 0.f);
    }
    __syncthreads();

    float acc[2][8][4] = {};
    mma_tile1<FAS, 8>(sb, F_A, F_B, acc, wid, lid);
    __syncthreads();

    // overlay: y = x + attn + c staged fp32 over dead A/B planes (stride 132)
    float* ybuf = (float*)smem;
    int wm = wid >> 1, wn = wid & 1;
    int arow = wm * 32, brow = wn * 64;
    #pragma unroll
    for (int mi = 0; mi < 2; mi++)
        #pragma unroll
        for (int n = 0; n < 8; n++) {
            int r = arow + mi * 16 + (lid >> 2);
            int c = brow + n * 8 + (lid & 3) * 2;
            float x0 = (c     < DIM) ? g_x[(size_t)(m0 + r) * DIM + c]     : 0.f;
            float x1v= (c + 1 < DIM) ? g_x[(size_t)(m0 + r) * DIM + c + 1] : 0.f;
            float x2 = (c     < DIM) ? g_x[(size_t)(m0 + r + 8) * DIM + c]     : 0.f;
            float x3 = (c + 1 < DIM) ? g_x[(size_t)(m0 + r + 8) * DIM + c + 1] : 0.f;
            ybuf[r * 132 + c]           = acc[mi][n][0] + x0  + cvec[c];
            ybuf[r * 132 + c + 1]       = acc[mi][n][1] + x1v + cvec[c + 1];
            ybuf[(r + 8) * 132 + c]     = acc[mi][n][2] + x2  + cvec[c];
            ybuf[(r + 8) * 132 + c + 1] = acc[mi][n][3] + x3  + cvec[c + 1];
        }
    __syncthreads();

    for (int rr = 0; rr < 16; rr++) {
        int r = wid * 16 + rr;
        float v[4], s = 0.f, sq = 0.f;
        #pragma unroll
        for (int q = 0; q < 4; q++) {
            int t = lid + q * 32;
            v[q] = (t < DIM) ? ybuf[r * 132 + t] : 0.f;
            s += v[q]; sq += v[q] * v[q];
        }
        #pragma unroll
        for (int off = 16; off; off >>= 1) {
            s  += __shfl_xor_sync(0xffffffffu, s,  off);
            sq += __shfl_xor_sync(0xffffffffu, sq, off);
        }
        float m = s / DIM;
        float inv = rsqrtf(sq / DIM - m * m + EPS);
        #pragma unroll
        for (int q = 0; q < 4; q++) {
            int t = lid + q * 32;
            float o = (t < DIM) ? (v[q] - m) * inv * ln1_g[t] + ln1_b[t] : 0.f;
            g_x1 [(size_t)(m0 + r) * KPAD + t] = o;
            g_x1f[(size_t)(m0 + r) * KPAD + t] = __float2half_rn(o);
        }
    }
}

// ---------------- K3: GEMM1: cp.async double-buffered K=64 stages -------------
#define AS1 72
#define PA1 (128 * AS1 * 2)            // 18432 per plane
#define STG1 (2 * PA1)                 // 36864 per stage (A+B)
#define S1_BIAS (2 * STG1)             // 73728
#define G1_SMEM (2 * STG1 + 512)

__global__ __launch_bounds__(256, 2)
void gemm1_mma(const float* __restrict__ b1) {
    extern __shared__ char smem[];
    uint32_t sb = smem_u32(smem);
    int tid = threadIdx.x, wid = tid >> 5, lid = tid & 31;
    int m0 = blockIdx.x * 128, n0 = blockIdx.y * 128;
    float* bias = (float*)(smem + S1_BIAS);
    if (tid < 128) bias[tid] = b1[n0 + tid];

    const uint4* A4 = (const uint4*)g_x1f + (size_t)m0 * 16;
    const uint4* B4 = (const uint4*)g_w1f + (size_t)n0 * 16;

    auto load_stage = [&](int kh, int buf) {
        uint32_t bb = sb + buf * STG1;
        #pragma unroll
        for (int i = 0; i < 4; i++) {
            int idx = tid + i * 256;
            int r = idx >> 3, c = idx & 7;
            uint32_t so = (uint32_t)((r * AS1 + c * 8) * 2);
            cp16(bb + so,       A4 + (size_t)r * 16 + kh * 8 + c);
            cp16(bb + PA1 + so, B4 + (size_t)r * 16 + kh * 8 + c);
        }
    };

    float acc[2][8][4] = {};
    load_stage(0, 0); CP_COMMIT();
    load_stage(1, 1); CP_COMMIT();
    cp_wait<1>();
    __syncthreads();
    mma_tile1<AS1, 4>(sb, 0, PA1, acc, wid, lid);
    cp_wait<0>();
    __syncthreads();
    mma_tile1<AS1, 4>(sb, STG1, STG1 + PA1, acc, wid, lid);
    __syncthreads();

    // epilogue: bias + relu -> fp16 plane via packed half2 stores (stride 136 halves)
    int wm = wid >> 1, wn = wid & 1;
    int arow = wm * 32, brow = wn * 64;
    __half2* sh2 = (__half2*)smem;          // 68 half2 per row
    #pragma unroll
    for (int mi = 0; mi < 2; mi++)
        #pragma unroll
        for (int n = 0; n < 8; n++) {
            int r = arow + mi * 16 + (lid >> 2);
            int c = brow + n * 8 + (lid & 3) * 2;
            float v0 = fmaxf(acc[mi][n][0] + bias[c], 0.f);
            float v1 = fmaxf(acc[mi][n][1] + bias[c + 1], 0.f);
            float v2 = fmaxf(acc[mi][n][2] + bias[c], 0.f);
            float v3 = fmaxf(acc[mi][n][3] + bias[c + 1], 0.f);
            sh2[r * 68 + (c >> 1)]       = __halves2half2(__float2half_rn(v0), __float2half_rn(v1));
            sh2[(r + 8) * 68 + (c >> 1)] = __halves2half2(__float2half_rn(v2), __float2half_rn(v3));
        }
    __syncthreads();
    uint4* HF = (uint4*)g_hf;
    #pragma unroll
    for (int i = 0; i < 8; i++) {
        int idx = tid + i * 256;
        int r = idx >> 4, c = idx & 15;
        uint32_t so = (uint32_t)((r * 136 + c * 8) * 2);
        HF[(size_t)(m0 + r) * 256 + (n0 >> 3) + c] = *(uint4*)(smem + so);
    }
}

// ---------------- K4: GEMM2: M-tile 64, K=32 double-buffered ------------------
#define AS2 40
#define ST_A (64 * AS2 * 2)            // 5120
#define ST_B (128 * AS2 * 2)           // 10240
#define BUF2 (ST_A + ST_B)             // 15360 per stage
#define S2_BIAS (2 * BUF2)
#define G2_SMEM (2 * BUF2 + 512)

__global__ __launch_bounds__(256, 2)
void gemm2_mma(const float* __restrict__ b2) {
    extern __shared__ char smem[];
    uint32_t sb = smem_u32(smem);
    int tid = threadIdx.x, wid = tid >> 5, lid = tid & 31;
    int m0 = blockIdx.x * 64;
    float* bias = (float*)(smem + S2_BIAS);
    if (tid < 128) bias[tid] = (tid < DIM) ? b2[tid] : 0.f;

    const uint4* srcA = (const uint4*)g_hf + (size_t)m0 * 256;
    const uint4* srcB = (const uint4*)g_w2f;

    auto load_chunk = [&](int c, int buf) {
        uint32_t bb = sb + buf * BUF2;
        {
            int r = tid >> 2, cc = tid & 3;
            uint32_t so = (uint32_t)((r * AS2 + cc * 8) * 2);
            cp16(bb + so, srcA + (size_t)r * 256 + c * 4 + cc);
        }
        #pragma unroll
        for (int i = 0; i < 2; i++) {
            int idx = tid + i * 256;
            int r = idx >> 2, cc = idx & 3;
            uint32_t so = (uint32_t)((r * AS2 + cc * 8) * 2);
            cp16(bb + ST_A + so, srcB + (size_t)r * 256 + c * 4 + cc);
        }
    };

    float acc[2][4][4] = {};
    load_chunk(0, 0);
    CP_COMMIT();

    for (int c = 0; c < 64; c++) {
        if (c + 1 < 64) {
            load_chunk(c + 1, (c + 1) & 1);
            CP_COMMIT();
            cp_wait<1>();
        } else {
            cp_wait<0>();
        }
        __syncthreads();
        uint32_t bb = sb + (c & 1) * BUF2;
        mma_tile64<AS2, 2>(bb, 0, ST_A, acc, wid, lid);
        __syncthreads();
    }

    int wm = wid >> 2, wn = wid & 3;
    int arow = wm * 32, brow = wn * 32;
    #pragma unroll
    for (int mi = 0; mi < 2; mi++)
        #pragma unroll
        for (int n = 0; n < 4; n++) {
            int gr = m0 + arow + mi * 16 + (lid >> 2);
            int cc = brow + n * 8 + (lid & 3) * 2;
            if (cc < DIM) {
                g_ff[(size_t)gr * DIM + cc]       = acc[mi][n][0] + bias[cc];
                g_ff[(size_t)(gr + 8) * DIM + cc] = acc[mi][n][2] + bias[cc];
            }
            if (cc + 1 < DIM) {
                g_ff[(size_t)gr * DIM + cc + 1]       = acc[mi][n][1] + bias[cc + 1];
                g_ff[(size_t)(gr + 8) * DIM + cc + 1] = acc[mi][n][3] + bias[cc + 1];
            }
        }
}

// ---------------- K5: fused LN2 + scoring ------------------------------------
__global__ __launch_bounds__(256, 2)
void ln2_score_tc(const float* __restrict__ ln2_g, const float* __restrict__ ln2_b,
                  const int* __restrict__ items, const float* __restrict__ rec_b,
                  float* __restrict__ out) {
    extern __shared__ char smem[];
    uint32_t sb = smem_u32(smem);
    int tid = threadIdx.x, wid = tid >> 5, lid = tid & 31;
    int m0 = blockIdx.x * 128;
    float* srecb = (float*)(smem + F_T);
    if (tid < KPAD) srecb[tid] = (tid < DIM) ? rec_b[tid] : 0.f;

    const uint4* B4 = (const uint4*)g_recf;
    #pragma unroll
    for (int i = 0; i < 8; i++) {
        int idx = tid + i * 256;
        int r = idx >> 4, c = idx & 15;
        uint32_t so = (uint32_t)((r * FAS + c * 8) * 2);
        *(uint4*)(smem + F_B + so) = B4[r * 16 + c];
    }

    for (int rr = 0; rr < 16; rr++) {
        int r = wid * 16 + rr;
        float v[4], s = 0.f, sq = 0.f;
        #pragma unroll
        for (int q = 0; q < 4; q++) {
            int t = lid + q * 32;
            v[q] = (t < DIM) ? g_x1[(size_t)(m0 + r) * KPAD + t]
                             + g_ff[(size_t)(m0 + r) * DIM + t] : 0.f;
            s += v[q]; sq += v[q] * v[q];
        }
        #pragma unroll
        for (int off = 16; off; off >>= 1) {
            s  += __shfl_xor_sync(0xffffffffu, s,  off);
            sq += __shfl_xor_sync(0xffffffffu, sq, off);
        }
        float m = s / DIM;
        float inv = rsqrtf(sq / DIM - m * m + EPS);
        #pragma unroll
        for (int q = 0; q < 4; q++) {
            int t = lid + q * 32;
            float o = (t < DIM) ? (v[q] - m) * inv * ln2_g[t] + ln2_b[t] : 0.f;
            *(fp16*)(smem + F_A + ((r * FAS + t) << 1)) = __float2half_rn(o);
        }
    }
    __syncthreads();

    float acc[2][8][4] = {};
    mma_tile1<FAS, 8>(sb, F_A, F_B, acc, wid, lid);
    __syncthreads();

    float* fbuf = (float*)smem;
    int wm = wid >> 1, wn = wid & 1;
    int arow = wm * 32, brow = wn * 64;
    #pragma unroll
    for (int mi = 0; mi < 2; mi++)
        #pragma unroll
        for (int n = 0; n < 8; n++) {
            int r = arow + mi * 16 + (lid >> 2);
            int c = brow + n * 8 + (lid & 3) * 2;
            fbuf[r * 128 + c]           = acc[mi][n][0];
            fbuf[r * 128 + c + 1]       = acc[mi][n][1];
            fbuf[(r + 8) * 128 + c]     = acc[mi][n][2];
            fbuf[(r + 8) * 128 + c + 1] = acc[mi][n][3];
        }
    __syncthreads();

    for (int o = tid; o < 128 * KPRED; o += 256) {
        int r = o / KPRED, k = o - r * KPRED;
        int idx = items[(size_t)(m0 + r) * KPRED + k];
        out[(size_t)(m0 + r) * KPRED + k] = fbuf[r * 128 + idx] + srecb[idx];
    }
}

// ---------------- launch ------------------------------------------------------
extern "C" void kernel_launch(void* const* d_in, const int* in_sizes, int n_in,
                              void* d_out, int out_size) {
    const int*   item_seq   = (const int*)  d_in[0];
    const int*   items_pred = (const int*)  d_in[1];
    const float* item_emb_w = (const float*)d_in[2];
    const float* rec_emb_w  = (const float*)d_in[3];
    const float* rec_b_w    = (const float*)d_in[4];
    const float* in_proj_w  = (const float*)d_in[5];
    const float* in_proj_b  = (const float*)d_in[6];
    const float* out_proj_w = (const float*)d_in[7];
    const float* out_proj_b = (const float*)d_in[8];
    const float* ln1_g      = (const float*)d_in[9];
    const float* ln1_b      = (const float*)d_in[10];
    const float* ln2_g      = (const float*)d_in[11];
    const float* ln2_b      = (const float*)d_in[12];
    const float* ffn_w1     = (const float*)d_in[13];
    const float* ffn_b1     = (const float*)d_in[14];
    const float* ffn_w2     = (const float*)d_in[15];
    const float* ffn_b2     = (const float*)d_in[16];
    float* out = (float*)d_out;

    int B = in_sizes[0] / SEQ_L;

    cudaFuncSetAttribute(attn_ln1_tc,  cudaFuncAttributeMaxDynamicSharedMemorySize, F_SMEM);
    cudaFuncSetAttribute(ln2_score_tc, cudaFuncAttributeMaxDynamicSharedMemorySize, F_SMEM);
    cudaFuncSetAttribute(gemm1_mma, cudaFuncAttributeMaxDynamicSharedMemorySize, G1_SMEM);
    cudaFuncSetAttribute(gemm2_mma, cudaFuncAttributeMaxDynamicSharedMemorySize, G2_SMEM);

    prep_all<<<2176, 256>>>(in_proj_w, in_proj_b, out_proj_w, out_proj_b,
                            rec_emb_w, ffn_w1, ffn_w2);
    attn_ln1_tc<<<B / 128, 256, F_SMEM>>>(item_seq, item_emb_w, ln1_g, ln1_b);
    gemm1_mma<<<dim3(B / 128, FFDIM / 128), 256, G1_SMEM>>>(ffn_b1);
    gemm2_mma<<<B / 64, 256, G2_SMEM>>>(ffn_b2);
    ln2_score_tc<<<B / 128, 256, F_SMEM>>>(ln2_g, ln2_b, items_pred, rec_b_w, out);
}

// round 11
// speedup vs baseline: 2.0285x; 2.0285x over previous
#include <cuda_runtime.h>
#include <cuda_fp16.h>
#include <cstdint>

#define SEQ_L 50
#define DIM 100
#define KPAD 128
#define FFDIM 2048
#define KPRED 100
#define EPS 1e-5f
#define BMAX 16384

typedef __half fp16;

// ---------------- scratch (device globals) ---------------------------------
__device__ float g_x  [BMAX * DIM];                   // embedding sums (residual)
__device__ float g_x1 [BMAX * KPAD];                  // LN1 out fp32 (residual)
__device__ float g_ff [BMAX * DIM];
__device__ float g_c  [KPAD];
__device__ fp16  g_Mf  [KPAD * KPAD];                 // attn matrix fp16
__device__ fp16  g_recf[KPAD * KPAD];                 // rec_emb fp16
__device__ fp16  g_x1f[BMAX * KPAD];                  // LN1 out fp16 (MMA operand)
__device__ fp16  g_w1f[FFDIM * KPAD];
__device__ fp16  g_hf [(size_t)BMAX * FFDIM];         // hidden fp16
__device__ fp16  g_w2f[KPAD * FFDIM];

// ---------------- helpers ----------------------------------------------------
__device__ __forceinline__ uint32_t smem_u32(const void* p) {
    uint32_t a;
    asm("{ .reg .u64 t; cvta.to.shared.u64 t, %1; cvt.u32.u64 %0, t; }" : "=r"(a) : "l"(p));
    return a;
}
__device__ __forceinline__ void ldsm_x4(uint32_t addr, uint32_t& r0, uint32_t& r1,
                                        uint32_t& r2, uint32_t& r3) {
    asm volatile("ldmatrix.sync.aligned.m8n8.x4.shared.b16 {%0,%1,%2,%3}, [%4];"
                 : "=r"(r0), "=r"(r1), "=r"(r2), "=r"(r3) : "r"(addr));
}
__device__ __forceinline__ void mma_f16(float* d, const uint32_t* a, const uint32_t* b) {
    asm volatile("mma.sync.aligned.m16n8k16.row.col.f32.f16.f16.f32 "
                 "{%0,%1,%2,%3}, {%4,%5,%6,%7}, {%8,%9}, {%0,%1,%2,%3};"
                 : "+f"(d[0]), "+f"(d[1]), "+f"(d[2]), "+f"(d[3])
                 : "r"(a[0]), "r"(a[1]), "r"(a[2]), "r"(a[3]), "r"(b[0]), "r"(b[1]));
}
__device__ __forceinline__ void cp16(uint32_t saddr, const void* g) {
    asm volatile("cp.async.cg.shared.global [%0], [%1], 16;" :: "r"(saddr), "l"(g));
}
#define CP_COMMIT() asm volatile("cp.async.commit_group;" ::: "memory")
template<int N> __device__ __forceinline__ void cp_wait() {
    asm volatile("cp.async.wait_group %0;" :: "n"(N) : "memory");
}

// 128x128 warp-tiled MMA phase (8 warps, warp tile 32x64)
template<int AS, int NKS>
__device__ __forceinline__ void mma_tile1(uint32_t sb, uint32_t oA, uint32_t oB,
                                          float acc[2][8][4], int wid, int lid) {
    int wm = wid >> 1, wn = wid & 1;
    int arow = wm * 32, brow = wn * 64;
    int lr = lid & 15, lc8 = (lid >> 4) << 3;
    #pragma unroll
    for (int ks = 0; ks < NKS; ks++) {
        int k0 = ks * 16;
        uint32_t a[2][4];
        #pragma unroll
        for (int mi = 0; mi < 2; mi++) {
            uint32_t off = (uint32_t)(((arow + mi * 16 + lr) * AS + k0 + lc8) * 2);
            ldsm_x4(sb + oA + off, a[mi][0], a[mi][1], a[mi][2], a[mi][3]);
        }
        uint32_t b[8][2];
        #pragma unroll
        for (int nj = 0; nj < 4; nj++) {
            uint32_t off = (uint32_t)(((brow + nj * 16 + lr) * AS + k0 + lc8) * 2);
            uint32_t r0, r1, r2, r3;
            ldsm_x4(sb + oB + off, r0, r1, r2, r3);
            b[nj * 2][0] = r0; b[nj * 2 + 1][0] = r1;
            b[nj * 2][1] = r2; b[nj * 2 + 1][1] = r3;
        }
        #pragma unroll
        for (int mi = 0; mi < 2; mi++)
            #pragma unroll
            for (int n = 0; n < 8; n++)
                mma_f16(acc[mi][n], a[mi], b[n]);
    }
}

// 32x128 warp-tiled MMA phase (8 warps, warp tile 32x16) — for gemm2
template<int AS, int NKS>
__device__ __forceinline__ void mma_tile32(uint32_t sb, uint32_t oA, uint32_t oB,
                                           float acc[2][2][4], int wid, int lid) {
    int brow = wid * 16;
    int lr = lid & 15, lc8 = (lid >> 4) << 3;
    #pragma unroll
    for (int ks = 0; ks < NKS; ks++) {
        int k0 = ks * 16;
        uint32_t a[2][4];
        #pragma unroll
        for (int mi = 0; mi < 2; mi++) {
            uint32_t off = (uint32_t)(((mi * 16 + lr) * AS + k0 + lc8) * 2);
            ldsm_x4(sb + oA + off, a[mi][0], a[mi][1], a[mi][2], a[mi][3]);
        }
        uint32_t b[2][2];
        {
            uint32_t off = (uint32_t)(((brow + lr) * AS + k0 + lc8) * 2);
            uint32_t r0, r1, r2, r3;
            ldsm_x4(sb + oB + off, r0, r1, r2, r3);
            b[0][0] = r0; b[1][0] = r1;
            b[0][1] = r2; b[1][1] = r3;
        }
        #pragma unroll
        for (int mi = 0; mi < 2; mi++)
            #pragma unroll
            for (int n = 0; n < 2; n++)
                mma_f16(acc[mi][n], a[mi], b[n]);
    }
}

// ---------------- K0: fused prep ---------------------------------------------
__global__ void prep_all(const float* __restrict__ in_proj_w,
                         const float* __restrict__ in_proj_b,
                         const float* __restrict__ out_proj_w,
                         const float* __restrict__ out_proj_b,
                         const float* __restrict__ rec_emb,
                         const float* __restrict__ w1,
                         const float* __restrict__ w2) {
    int bid = blockIdx.x, tid = threadIdx.x;
    if (bid < 64) {
        int i = bid * 2 + (tid >> 7);
        int j = tid & 127;
        const float* Wv = in_proj_w + 2 * DIM * DIM;
        const float* bv = in_proj_b + 2 * DIM;
        float mv = 0.f;
        if (i < DIM && j < DIM) {
            #pragma unroll 4
            for (int k = 0; k < DIM; k++)
                mv += out_proj_w[i * DIM + k] * Wv[k * DIM + j];
        }
        g_Mf[i * KPAD + j] = __float2half_rn(mv);
        if (j == 0) {
            float s = 0.f;
            if (i < DIM) {
                s = out_proj_b[i];
                for (int k = 0; k < DIM; k++)
                    s += out_proj_w[i * DIM + k] * bv[k];
            }
            g_c[i] = s;
        }
    } else if (bid < 128) {
        int idx = (bid - 64) * 256 + tid;
        int n = idx >> 7, k = idx & 127;
        float v = (n < DIM && k < DIM) ? rec_emb[n * DIM + k] : 0.f;
        g_recf[idx] = __float2half_rn(v);
    } else if (bid < 128 + 1024) {
        int idx = (bid - 128) * 256 + tid;
        int n = idx >> 7, k = idx & 127;
        float v = (k < DIM) ? w1[n * DIM + k] : 0.f;
        g_w1f[idx] = __float2half_rn(v);
    } else {
        int idx = (bid - 1152) * 256 + tid;
        int n = idx >> 11, k = idx & 2047;
        float v = (n < DIM) ? w2[n * FFDIM + k] : 0.f;
        g_w2f[idx] = __float2half_rn(v);
    }
}

// ---------------- K1: embedding gather-sum (16384 CTAs — proven) --------------
__global__ void embed_sum(const int* __restrict__ seq,
                          const float* __restrict__ emb) {
    int b = blockIdx.x;
    __shared__ int s_idx[SEQ_L];
    int t = threadIdx.x;
    if (t < SEQ_L) s_idx[t] = seq[b * SEQ_L + t];
    __syncthreads();
    if (t < DIM) {
        float acc = 0.f;
        #pragma unroll 5
        for (int l = 0; l < SEQ_L; l++)
            acc += emb[(size_t)s_idx[l] * DIM + t];
        g_x[b * DIM + t] = acc;
    }
}

// ---------------- fused-tile smem layout (attn_ln1 / ln2_score) -------------
#define FAS 136
#define PL_SZ (128 * FAS * 2)          // 34816
#define F_A  0
#define F_B  PL_SZ
#define F_T  (2 * PL_SZ)
#define F_SMEM (2 * PL_SZ + 512)       // 70144 -> occ 2

// ---------------- K2: fused attn + LN1 (R8 version) ---------------------------
__global__ __launch_bounds__(256, 2)
void attn_ln1_tc(const float* __restrict__ ln1_g, const float* __restrict__ ln1_b) {
    extern __shared__ char smem[];
    uint32_t sb = smem_u32(smem);
    int tid = threadIdx.x, wid = tid >> 5, lid = tid & 31;
    int m0 = blockIdx.x * 128;
    float* cvec = (float*)(smem + F_T);
    if (tid < KPAD) cvec[tid] = g_c[tid];

    for (int idx = tid; idx < 128 * 128; idx += 256) {
        int r = idx >> 7, j = idx & 127;
        float v = (j < DIM) ? g_x[(size_t)(m0 + r) * DIM + j] : 0.f;
        *(fp16*)(smem + F_A + ((r * FAS + j) << 1)) = __float2half_rn(v);
    }
    const uint4* B4 = (const uint4*)g_Mf;
    #pragma unroll
    for (int i = 0; i < 8; i++) {
        int idx = tid + i * 256;
        int r = idx >> 4, c = idx & 15;
        uint32_t so = (uint32_t)((r * FAS + c * 8) * 2);
        *(uint4*)(smem + F_B + so) = B4[r * 16 + c];
    }
    __syncthreads();

    float acc[2][8][4] = {};
    mma_tile1<FAS, 8>(sb, F_A, F_B, acc, wid, lid);
    __syncthreads();

    float* ybuf = (float*)smem;            // overlay, stride 132
    int wm = wid >> 1, wn = wid & 1;
    int arow = wm * 32, brow = wn * 64;
    #pragma unroll
    for (int mi = 0; mi < 2; mi++)
        #pragma unroll
        for (int n = 0; n < 8; n++) {
            int r = arow + mi * 16 + (lid >> 2);
            int c = brow + n * 8 + (lid & 3) * 2;
            float x0 = (c     < DIM) ? g_x[(size_t)(m0 + r) * DIM + c]     : 0.f;
            float x1v= (c + 1 < DIM) ? g_x[(size_t)(m0 + r) * DIM + c + 1] : 0.f;
            float x2 = (c     < DIM) ? g_x[(size_t)(m0 + r + 8) * DIM + c]     : 0.f;
            float x3 = (c + 1 < DIM) ? g_x[(size_t)(m0 + r + 8) * DIM + c + 1] : 0.f;
            ybuf[r * 132 + c]           = acc[mi][n][0] + x0  + cvec[c];
            ybuf[r * 132 + c + 1]       = acc[mi][n][1] + x1v + cvec[c + 1];
            ybuf[(r + 8) * 132 + c]     = acc[mi][n][2] + x2  + cvec[c];
            ybuf[(r + 8) * 132 + c + 1] = acc[mi][n][3] + x3  + cvec[c + 1];
        }
    __syncthreads();

    for (int rr = 0; rr < 16; rr++) {
        int r = wid * 16 + rr;
        float v[4], s = 0.f, sq = 0.f;
        #pragma unroll
        for (int q = 0; q < 4; q++) {
            int t = lid + q * 32;
            v[q] = (t < DIM) ? ybuf[r * 132 + t] : 0.f;
            s += v[q]; sq += v[q] * v[q];
        }
        #pragma unroll
        for (int off = 16; off; off >>= 1) {
            s  += __shfl_xor_sync(0xffffffffu, s,  off);
            sq += __shfl_xor_sync(0xffffffffu, sq, off);
        }
        float m = s / DIM;
        float inv = rsqrtf(sq / DIM - m * m + EPS);
        #pragma unroll
        for (int q = 0; q < 4; q++) {
            int t = lid + q * 32;
            float o = (t < DIM) ? (v[q] - m) * inv * ln1_g[t] + ln1_b[t] : 0.f;
            g_x1 [(size_t)(m0 + r) * KPAD + t] = o;
            g_x1f[(size_t)(m0 + r) * KPAD + t] = __float2half_rn(o);
        }
    }
}

// ---------------- K3: GEMM1: cp.async double-buffered K=64 stages -------------
#define AS1 72
#define PA1 (128 * AS1 * 2)            // 18432 per plane
#define STG1 (2 * PA1)                 // 36864 per stage (A+B)
#define S1_BIAS (2 * STG1)             // 73728
#define G1_SMEM (2 * STG1 + 512)

__global__ __launch_bounds__(256, 2)
void gemm1_mma(const float* __restrict__ b1) {
    extern __shared__ char smem[];
    uint32_t sb = smem_u32(smem);
    int tid = threadIdx.x, wid = tid >> 5, lid = tid & 31;
    int m0 = blockIdx.x * 128, n0 = blockIdx.y * 128;
    float* bias = (float*)(smem + S1_BIAS);
    if (tid < 128) bias[tid] = b1[n0 + tid];

    const uint4* A4 = (const uint4*)g_x1f + (size_t)m0 * 16;
    const uint4* B4 = (const uint4*)g_w1f + (size_t)n0 * 16;

    auto load_stage = [&](int kh, int buf) {
        uint32_t bb = sb + buf * STG1;
        #pragma unroll
        for (int i = 0; i < 4; i++) {
            int idx = tid + i * 256;
            int r = idx >> 3, c = idx & 7;
            uint32_t so = (uint32_t)((r * AS1 + c * 8) * 2);
            cp16(bb + so,       A4 + (size_t)r * 16 + kh * 8 + c);
            cp16(bb + PA1 + so, B4 + (size_t)r * 16 + kh * 8 + c);
        }
    };

    float acc[2][8][4] = {};
    load_stage(0, 0); CP_COMMIT();
    load_stage(1, 1); CP_COMMIT();
    cp_wait<1>();
    __syncthreads();
    mma_tile1<AS1, 4>(sb, 0, PA1, acc, wid, lid);
    cp_wait<0>();
    __syncthreads();
    mma_tile1<AS1, 4>(sb, STG1, STG1 + PA1, acc, wid, lid);
    __syncthreads();

    // epilogue: bias + relu -> fp16 plane via packed half2 stores (stride 136 halves)
    int wm = wid >> 1, wn = wid & 1;
    int arow = wm * 32, brow = wn * 64;
    __half2* sh2 = (__half2*)smem;          // 68 half2 per row
    #pragma unroll
    for (int mi = 0; mi < 2; mi++)
        #pragma unroll
        for (int n = 0; n < 8; n++) {
            int r = arow + mi * 16 + (lid >> 2);
            int c = brow + n * 8 + (lid & 3) * 2;
            float v0 = fmaxf(acc[mi][n][0] + bias[c], 0.f);
            float v1 = fmaxf(acc[mi][n][1] + bias[c + 1], 0.f);
            float v2 = fmaxf(acc[mi][n][2] + bias[c], 0.f);
            float v3 = fmaxf(acc[mi][n][3] + bias[c + 1], 0.f);
            sh2[r * 68 + (c >> 1)]       = __halves2half2(__float2half_rn(v0), __float2half_rn(v1));
            sh2[(r + 8) * 68 + (c >> 1)] = __halves2half2(__float2half_rn(v2), __float2half_rn(v3));
        }
    __syncthreads();
    uint4* HF = (uint4*)g_hf;
    #pragma unroll
    for (int i = 0; i < 8; i++) {
        int idx = tid + i * 256;
        int r = idx >> 4, c = idx & 15;
        uint32_t so = (uint32_t)((r * 136 + c * 8) * 2);
        HF[(size_t)(m0 + r) * 256 + (n0 >> 3) + c] = *(uint4*)(smem + so);
    }
}

// ---------------- K4: GEMM2: M-tile 32 -> 512 CTAs, K=32 double-buffered ------
#define AS2 40
#define ST_A32 (32 * AS2 * 2)          // 2560
#define ST_B32 (128 * AS2 * 2)         // 10240
#define BUF2 (ST_A32 + ST_B32)         // 12800 per stage
#define S2_BIAS (2 * BUF2)             // 25600
#define G2_SMEM (2 * BUF2 + 512)

__global__ __launch_bounds__(256, 3)
void gemm2_mma(const float* __restrict__ b2) {
    extern __shared__ char smem[];
    uint32_t sb = smem_u32(smem);
    int tid = threadIdx.x, wid = tid >> 5, lid = tid & 31;
    int m0 = blockIdx.x * 32;
    float* bias = (float*)(smem + S2_BIAS);
    if (tid < 128) bias[tid] = (tid < DIM) ? b2[tid] : 0.f;

    const uint4* srcA = (const uint4*)g_hf + (size_t)m0 * 256;
    const uint4* srcB = (const uint4*)g_w2f;

    auto load_chunk = [&](int c, int buf) {
        uint32_t bb = sb + buf * BUF2;
        if (tid < 128) {                  // A: 32 rows x 4 uint4
            int r = tid >> 2, cc = tid & 3;
            uint32_t so = (uint32_t)((r * AS2 + cc * 8) * 2);
            cp16(bb + so, srcA + (size_t)r * 256 + c * 4 + cc);
        }
        #pragma unroll
        for (int i = 0; i < 2; i++) {     // B: 128 rows x 4 uint4
            int idx = tid + i * 256;
            int r = idx >> 2, cc = idx & 3;
            uint32_t so = (uint32_t)((r * AS2 + cc * 8) * 2);
            cp16(bb + ST_A32 + so, srcB + (size_t)r * 256 + c * 4 + cc);
        }
    };

    float acc[2][2][4] = {};
    load_chunk(0, 0);
    CP_COMMIT();

    for (int c = 0; c < 64; c++) {
        if (c + 1 < 64) {
            load_chunk(c + 1, (c + 1) & 1);
            CP_COMMIT();
            cp_wait<1>();
        } else {
            cp_wait<0>();
        }
        __syncthreads();
        uint32_t bb = sb + (c & 1) * BUF2;
        mma_tile32<AS2, 2>(bb, 0, ST_A32, acc, wid, lid);
        __syncthreads();
    }

    int brow = wid * 16;
    #pragma unroll
    for (int mi = 0; mi < 2; mi++)
        #pragma unroll
        for (int n = 0; n < 2; n++) {
            int gr = m0 + mi * 16 + (lid >> 2);
            int cc = brow + n * 8 + (lid & 3) * 2;
            if (cc < DIM) {
                g_ff[(size_t)gr * DIM + cc]       = acc[mi][n][0] + bias[cc];
                g_ff[(size_t)(gr + 8) * DIM + cc] = acc[mi][n][2] + bias[cc];
            }
            if (cc + 1 < DIM) {
                g_ff[(size_t)gr * DIM + cc + 1]       = acc[mi][n][1] + bias[cc + 1];
                g_ff[(size_t)(gr + 8) * DIM + cc + 1] = acc[mi][n][3] + bias[cc + 1];
            }
        }
}

// ---------------- K5: fused LN2 + scoring ------------------------------------
__global__ __launch_bounds__(256, 2)
void ln2_score_tc(const float* __restrict__ ln2_g, const float* __restrict__ ln2_b,
                  const int* __restrict__ items, const float* __restrict__ rec_b,
                  float* __restrict__ out) {
    extern __shared__ char smem[];
    uint32_t sb = smem_u32(smem);
    int tid = threadIdx.x, wid = tid >> 5, lid = tid & 31;
    int m0 = blockIdx.x * 128;
    float* srecb = (float*)(smem + F_T);
    if (tid < KPAD) srecb[tid] = (tid < DIM) ? rec_b[tid] : 0.f;

    const uint4* B4 = (const uint4*)g_recf;
    #pragma unroll
    for (int i = 0; i < 8; i++) {
        int idx = tid + i * 256;
        int r = idx >> 4, c = idx & 15;
        uint32_t so = (uint32_t)((r * FAS + c * 8) * 2);
        *(uint4*)(smem + F_B + so) = B4[r * 16 + c];
    }

    for (int rr = 0; rr < 16; rr++) {
        int r = wid * 16 + rr;
        float v[4], s = 0.f, sq = 0.f;
        #pragma unroll
        for (int q = 0; q < 4; q++) {
            int t = lid + q * 32;
            v[q] = (t < DIM) ? g_x1[(size_t)(m0 + r) * KPAD + t]
                             + g_ff[(size_t)(m0 + r) * DIM + t] : 0.f;
            s += v[q]; sq += v[q] * v[q];
        }
        #pragma unroll
        for (int off = 16; off; off >>= 1) {
            s  += __shfl_xor_sync(0xffffffffu, s,  off);
            sq += __shfl_xor_sync(0xffffffffu, sq, off);
        }
        float m = s / DIM;
        float inv = rsqrtf(sq / DIM - m * m + EPS);
        #pragma unroll
        for (int q = 0; q < 4; q++) {
            int t = lid + q * 32;
            float o = (t < DIM) ? (v[q] - m) * inv * ln2_g[t] + ln2_b[t] : 0.f;
            *(fp16*)(smem + F_A + ((r * FAS + t) << 1)) = __float2half_rn(o);
        }
    }
    __syncthreads();

    float acc[2][8][4] = {};
    mma_tile1<FAS, 8>(sb, F_A, F_B, acc, wid, lid);
    __syncthreads();

    float* fbuf = (float*)smem;
    int wm = wid >> 1, wn = wid & 1;
    int arow = wm * 32, brow = wn * 64;
    #pragma unroll
    for (int mi = 0; mi < 2; mi++)
        #pragma unroll
        for (int n = 0; n < 8; n++) {
            int r = arow + mi * 16 + (lid >> 2);
            int c = brow + n * 8 + (lid & 3) * 2;
            fbuf[r * 128 + c]           = acc[mi][n][0];
            fbuf[r * 128 + c + 1]       = acc[mi][n][1];
            fbuf[(r + 8) * 128 + c]     = acc[mi][n][2];
            fbuf[(r + 8) * 128 + c + 1] = acc[mi][n][3];
        }
    __syncthreads();

    for (int o = tid; o < 128 * KPRED; o += 256) {
        int r = o / KPRED, k = o - r * KPRED;
        int idx = items[(size_t)(m0 + r) * KPRED + k];
        out[(size_t)(m0 + r) * KPRED + k] = fbuf[r * 128 + idx] + srecb[idx];
    }
}

// ---------------- launch ------------------------------------------------------
extern "C" void kernel_launch(void* const* d_in, const int* in_sizes, int n_in,
                              void* d_out, int out_size) {
    const int*   item_seq   = (const int*)  d_in[0];
    const int*   items_pred = (const int*)  d_in[1];
    const float* item_emb_w = (const float*)d_in[2];
    const float* rec_emb_w  = (const float*)d_in[3];
    const float* rec_b_w    = (const float*)d_in[4];
    const float* in_proj_w  = (const float*)d_in[5];
    const float* in_proj_b  = (const float*)d_in[6];
    const float* out_proj_w = (const float*)d_in[7];
    const float* out_proj_b = (const float*)d_in[8];
    const float* ln1_g      = (const float*)d_in[9];
    const float* ln1_b      = (const float*)d_in[10];
    const float* ln2_g      = (const float*)d_in[11];
    const float* ln2_b      = (const float*)d_in[12];
    const float* ffn_w1     = (const float*)d_in[13];
    const float* ffn_b1     = (const float*)d_in[14];
    const float* ffn_w2     = (const float*)d_in[15];
    const float* ffn_b2     = (const float*)d_in[16];
    float* out = (float*)d_out;

    int B = in_sizes[0] / SEQ_L;

    cudaFuncSetAttribute(attn_ln1_tc,  cudaFuncAttributeMaxDynamicSharedMemorySize, F_SMEM);
    cudaFuncSetAttribute(ln2_score_tc, cudaFuncAttributeMaxDynamicSharedMemorySize, F_SMEM);
    cudaFuncSetAttribute(gemm1_mma, cudaFuncAttributeMaxDynamicSharedMemorySize, G1_SMEM);
    cudaFuncSetAttribute(gemm2_mma, cudaFuncAttributeMaxDynamicSharedMemorySize, G2_SMEM);

    prep_all<<<2176, 256>>>(in_proj_w, in_proj_b, out_proj_w, out_proj_b,
                            rec_emb_w, ffn_w1, ffn_w2);
    embed_sum<<<B, 128>>>(item_seq, item_emb_w);
    attn_ln1_tc<<<B / 128, 256, F_SMEM>>>(ln1_g, ln1_b);
    gemm1_mma<<<dim3(B / 128, FFDIM / 128), 256, G1_SMEM>>>(ffn_b1);
    gemm2_mma<<<B / 32, 256, G2_SMEM>>>(ffn_b2);
    ln2_score_tc<<<B / 128, 256, F_SMEM>>>(ln2_g, ln2_b, items_pred, rec_b_w, out);
}

// round 12
// speedup vs baseline: 2.1950x; 1.0820x over previous
#include <cuda_runtime.h>
#include <cuda_fp16.h>
#include <cstdint>

#define SEQ_L 50
#define DIM 100
#define KPAD 128
#define FFDIM 2048
#define KPRED 100
#define EPS 1e-5f
#define BMAX 16384

typedef __half fp16;

// ---------------- scratch (device globals) ---------------------------------
__device__ float g_x  [BMAX * DIM];                   // embedding sums (residual)
__device__ float g_x1 [BMAX * KPAD];                  // LN1 out fp32 (residual)
__device__ float g_ff0[BMAX * DIM];                   // FFN out, K-split half 0
__device__ float g_ff1[BMAX * DIM];                   // FFN out, K-split half 1
__device__ float g_c  [KPAD];
__device__ fp16  g_Mf  [KPAD * KPAD];                 // attn matrix fp16
__device__ fp16  g_recf[KPAD * KPAD];                 // rec_emb fp16
__device__ fp16  g_x1f[BMAX * KPAD];                  // LN1 out fp16 (MMA operand)
__device__ fp16  g_w1f[FFDIM * KPAD];
__device__ fp16  g_hf [(size_t)BMAX * FFDIM];         // hidden fp16
__device__ fp16  g_w2f[KPAD * FFDIM];

// ---------------- helpers ----------------------------------------------------
__device__ __forceinline__ uint32_t smem_u32(const void* p) {
    uint32_t a;
    asm("{ .reg .u64 t; cvta.to.shared.u64 t, %1; cvt.u32.u64 %0, t; }" : "=r"(a) : "l"(p));
    return a;
}
__device__ __forceinline__ void ldsm_x4(uint32_t addr, uint32_t& r0, uint32_t& r1,
                                        uint32_t& r2, uint32_t& r3) {
    asm volatile("ldmatrix.sync.aligned.m8n8.x4.shared.b16 {%0,%1,%2,%3}, [%4];"
                 : "=r"(r0), "=r"(r1), "=r"(r2), "=r"(r3) : "r"(addr));
}
__device__ __forceinline__ void mma_f16(float* d, const uint32_t* a, const uint32_t* b) {
    asm volatile("mma.sync.aligned.m16n8k16.row.col.f32.f16.f16.f32 "
                 "{%0,%1,%2,%3}, {%4,%5,%6,%7}, {%8,%9}, {%0,%1,%2,%3};"
                 : "+f"(d[0]), "+f"(d[1]), "+f"(d[2]), "+f"(d[3])
                 : "r"(a[0]), "r"(a[1]), "r"(a[2]), "r"(a[3]), "r"(b[0]), "r"(b[1]));
}
__device__ __forceinline__ void cp16(uint32_t saddr, const void* g) {
    asm volatile("cp.async.cg.shared.global [%0], [%1], 16;" :: "r"(saddr), "l"(g));
}
#define CP_COMMIT() asm volatile("cp.async.commit_group;" ::: "memory")
template<int N> __device__ __forceinline__ void cp_wait() {
    asm volatile("cp.async.wait_group %0;" :: "n"(N) : "memory");
}

// 128x128 warp-tiled MMA phase (8 warps, warp tile 32x64)
template<int AS, int NKS>
__device__ __forceinline__ void mma_tile1(uint32_t sb, uint32_t oA, uint32_t oB,
                                          float acc[2][8][4], int wid, int lid) {
    int wm = wid >> 1, wn = wid & 1;
    int arow = wm * 32, brow = wn * 64;
    int lr = lid & 15, lc8 = (lid >> 4) << 3;
    #pragma unroll
    for (int ks = 0; ks < NKS; ks++) {
        int k0 = ks * 16;
        uint32_t a[2][4];
        #pragma unroll
        for (int mi = 0; mi < 2; mi++) {
            uint32_t off = (uint32_t)(((arow + mi * 16 + lr) * AS + k0 + lc8) * 2);
            ldsm_x4(sb + oA + off, a[mi][0], a[mi][1], a[mi][2], a[mi][3]);
        }
        uint32_t b[8][2];
        #pragma unroll
        for (int nj = 0; nj < 4; nj++) {
            uint32_t off = (uint32_t)(((brow + nj * 16 + lr) * AS + k0 + lc8) * 2);
            uint32_t r0, r1, r2, r3;
            ldsm_x4(sb + oB + off, r0, r1, r2, r3);
            b[nj * 2][0] = r0; b[nj * 2 + 1][0] = r1;
            b[nj * 2][1] = r2; b[nj * 2 + 1][1] = r3;
        }
        #pragma unroll
        for (int mi = 0; mi < 2; mi++)
            #pragma unroll
            for (int n = 0; n < 8; n++)
                mma_f16(acc[mi][n], a[mi], b[n]);
    }
}

// 64x128 warp-tiled MMA phase (8 warps, warp tile 32x32) — for gemm2
template<int AS, int NKS>
__device__ __forceinline__ void mma_tile64(uint32_t sb, uint32_t oA, uint32_t oB,
                                           float acc[2][4][4], int wid, int lid) {
    int wm = wid >> 2, wn = wid & 3;
    int arow = wm * 32, brow = wn * 32;
    int lr = lid & 15, lc8 = (lid >> 4) << 3;
    #pragma unroll
    for (int ks = 0; ks < NKS; ks++) {
        int k0 = ks * 16;
        uint32_t a[2][4];
        #pragma unroll
        for (int mi = 0; mi < 2; mi++) {
            uint32_t off = (uint32_t)(((arow + mi * 16 + lr) * AS + k0 + lc8) * 2);
            ldsm_x4(sb + oA + off, a[mi][0], a[mi][1], a[mi][2], a[mi][3]);
        }
        uint32_t b[4][2];
        #pragma unroll
        for (int nj = 0; nj < 2; nj++) {
            uint32_t off = (uint32_t)(((brow + nj * 16 + lr) * AS + k0 + lc8) * 2);
            uint32_t r0, r1, r2, r3;
            ldsm_x4(sb + oB + off, r0, r1, r2, r3);
            b[nj * 2][0] = r0; b[nj * 2 + 1][0] = r1;
            b[nj * 2][1] = r2; b[nj * 2 + 1][1] = r3;
        }
        #pragma unroll
        for (int mi = 0; mi < 2; mi++)
            #pragma unroll
            for (int n = 0; n < 4; n++)
                mma_f16(acc[mi][n], a[mi], b[n]);
    }
}

// ---------------- K0: fused prep ---------------------------------------------
__global__ void prep_all(const float* __restrict__ in_proj_w,
                         const float* __restrict__ in_proj_b,
                         const float* __restrict__ out_proj_w,
                         const float* __restrict__ out_proj_b,
                         const float* __restrict__ rec_emb,
                         const float* __restrict__ w1,
                         const float* __restrict__ w2) {
    int bid = blockIdx.x, tid = threadIdx.x;
    if (bid < 64) {
        int i = bid * 2 + (tid >> 7);
        int j = tid & 127;
        const float* Wv = in_proj_w + 2 * DIM * DIM;
        const float* bv = in_proj_b + 2 * DIM;
        float mv = 0.f;
        if (i < DIM && j < DIM) {
            #pragma unroll 4
            for (int k = 0; k < DIM; k++)
                mv += out_proj_w[i * DIM + k] * Wv[k * DIM + j];
        }
        g_Mf[i * KPAD + j] = __float2half_rn(mv);
        if (j == 0) {
            float s = 0.f;
            if (i < DIM) {
                s = out_proj_b[i];
                for (int k = 0; k < DIM; k++)
                    s += out_proj_w[i * DIM + k] * bv[k];
            }
            g_c[i] = s;
        }
    } else if (bid < 128) {
        int idx = (bid - 64) * 256 + tid;
        int n = idx >> 7, k = idx & 127;
        float v = (n < DIM && k < DIM) ? rec_emb[n * DIM + k] : 0.f;
        g_recf[idx] = __float2half_rn(v);
    } else if (bid < 128 + 1024) {
        int idx = (bid - 128) * 256 + tid;
        int n = idx >> 7, k = idx & 127;
        float v = (k < DIM) ? w1[n * DIM + k] : 0.f;
        g_w1f[idx] = __float2half_rn(v);
    } else {
        int idx = (bid - 1152) * 256 + tid;
        int n = idx >> 11, k = idx & 2047;
        float v = (n < DIM) ? w2[n * FFDIM + k] : 0.f;
        g_w2f[idx] = __float2half_rn(v);
    }
}

// ---------------- K1: embedding gather-sum (16384 CTAs — proven) --------------
__global__ void embed_sum(const int* __restrict__ seq,
                          const float* __restrict__ emb) {
    int b = blockIdx.x;
    __shared__ int s_idx[SEQ_L];
    int t = threadIdx.x;
    if (t < SEQ_L) s_idx[t] = seq[b * SEQ_L + t];
    __syncthreads();
    if (t < DIM) {
        float acc = 0.f;
        #pragma unroll 5
        for (int l = 0; l < SEQ_L; l++)
            acc += emb[(size_t)s_idx[l] * DIM + t];
        g_x[b * DIM + t] = acc;
    }
}

// ---------------- fused-tile smem layout (attn_ln1 / ln2_score) -------------
#define FAS 136
#define PL_SZ (128 * FAS * 2)          // 34816
#define F_A  0
#define F_B  PL_SZ
#define F_T  (2 * PL_SZ)               // tail: 2x128 floats
#define F_SMEM (2 * PL_SZ + 1024)      // 70656 -> occ 2

// ---------------- K2: fused attn + LN1 ----------------------------------------
__global__ __launch_bounds__(256, 2)
void attn_ln1_tc(const float* __restrict__ ln1_g, const float* __restrict__ ln1_b) {
    extern __shared__ char smem[];
    uint32_t sb = smem_u32(smem);
    int tid = threadIdx.x, wid = tid >> 5, lid = tid & 31;
    int m0 = blockIdx.x * 128;
    float* cvec = (float*)(smem + F_T);
    if (tid < KPAD) cvec[tid] = g_c[tid];

    for (int idx = tid; idx < 128 * 128; idx += 256) {
        int r = idx >> 7, j = idx & 127;
        float v = (j < DIM) ? g_x[(size_t)(m0 + r) * DIM + j] : 0.f;
        *(fp16*)(smem + F_A + ((r * FAS + j) << 1)) = __float2half_rn(v);
    }
    const uint4* B4 = (const uint4*)g_Mf;
    #pragma unroll
    for (int i = 0; i < 8; i++) {
        int idx = tid + i * 256;
        int r = idx >> 4, c = idx & 15;
        uint32_t so = (uint32_t)((r * FAS + c * 8) * 2);
        *(uint4*)(smem + F_B + so) = B4[r * 16 + c];
    }
    __syncthreads();

    float acc[2][8][4] = {};
    mma_tile1<FAS, 8>(sb, F_A, F_B, acc, wid, lid);
    __syncthreads();

    float* ybuf = (float*)smem;            // overlay, stride 132
    int wm = wid >> 1, wn = wid & 1;
    int arow = wm * 32, brow = wn * 64;
    #pragma unroll
    for (int mi = 0; mi < 2; mi++)
        #pragma unroll
        for (int n = 0; n < 8; n++) {
            int r = arow + mi * 16 + (lid >> 2);
            int c = brow + n * 8 + (lid & 3) * 2;
            float x0 = (c     < DIM) ? g_x[(size_t)(m0 + r) * DIM + c]     : 0.f;
            float x1v= (c + 1 < DIM) ? g_x[(size_t)(m0 + r) * DIM + c + 1] : 0.f;
            float x2 = (c     < DIM) ? g_x[(size_t)(m0 + r + 8) * DIM + c]     : 0.f;
            float x3 = (c + 1 < DIM) ? g_x[(size_t)(m0 + r + 8) * DIM + c + 1] : 0.f;
            ybuf[r * 132 + c]           = acc[mi][n][0] + x0  + cvec[c];
            ybuf[r * 132 + c + 1]       = acc[mi][n][1] + x1v + cvec[c + 1];
            ybuf[(r + 8) * 132 + c]     = acc[mi][n][2] + x2  + cvec[c];
            ybuf[(r + 8) * 132 + c + 1] = acc[mi][n][3] + x3  + cvec[c + 1];
        }
    __syncthreads();

    for (int rr = 0; rr < 16; rr++) {
        int r = wid * 16 + rr;
        float v[4], s = 0.f, sq = 0.f;
        #pragma unroll
        for (int q = 0; q < 4; q++) {
            int t = lid + q * 32;
            v[q] = (t < DIM) ? ybuf[r * 132 + t] : 0.f;
            s += v[q]; sq += v[q] * v[q];
        }
        #pragma unroll
        for (int off = 16; off; off >>= 1) {
            s  += __shfl_xor_sync(0xffffffffu, s,  off);
            sq += __shfl_xor_sync(0xffffffffu, sq, off);
        }
        float m = s / DIM;
        float inv = rsqrtf(sq / DIM - m * m + EPS);
        #pragma unroll
        for (int q = 0; q < 4; q++) {
            int t = lid + q * 32;
            float o = (t < DIM) ? (v[q] - m) * inv * ln1_g[t] + ln1_b[t] : 0.f;
            g_x1 [(size_t)(m0 + r) * KPAD + t] = o;
            g_x1f[(size_t)(m0 + r) * KPAD + t] = __float2half_rn(o);
        }
    }
}

// ---------------- K3: GEMM1: cp.async double-buffered K=64 stages -------------
#define AS1 72
#define PA1 (128 * AS1 * 2)            // 18432 per plane
#define STG1 (2 * PA1)                 // 36864 per stage (A+B)
#define S1_BIAS (2 * STG1)             // 73728
#define G1_SMEM (2 * STG1 + 512)

__global__ __launch_bounds__(256, 2)
void gemm1_mma(const float* __restrict__ b1) {
    extern __shared__ char smem[];
    uint32_t sb = smem_u32(smem);
    int tid = threadIdx.x, wid = tid >> 5, lid = tid & 31;
    int m0 = blockIdx.x * 128, n0 = blockIdx.y * 128;
    float* bias = (float*)(smem + S1_BIAS);
    if (tid < 128) bias[tid] = b1[n0 + tid];

    const uint4* A4 = (const uint4*)g_x1f + (size_t)m0 * 16;
    const uint4* B4 = (const uint4*)g_w1f + (size_t)n0 * 16;

    auto load_stage = [&](int kh, int buf) {
        uint32_t bb = sb + buf * STG1;
        #pragma unroll
        for (int i = 0; i < 4; i++) {
            int idx = tid + i * 256;
            int r = idx >> 3, c = idx & 7;
            uint32_t so = (uint32_t)((r * AS1 + c * 8) * 2);
            cp16(bb + so,       A4 + (size_t)r * 16 + kh * 8 + c);
            cp16(bb + PA1 + so, B4 + (size_t)r * 16 + kh * 8 + c);
        }
    };

    float acc[2][8][4] = {};
    load_stage(0, 0); CP_COMMIT();
    load_stage(1, 1); CP_COMMIT();
    cp_wait<1>();
    __syncthreads();
    mma_tile1<AS1, 4>(sb, 0, PA1, acc, wid, lid);
    cp_wait<0>();
    __syncthreads();
    mma_tile1<AS1, 4>(sb, STG1, STG1 + PA1, acc, wid, lid);
    __syncthreads();

    // epilogue: bias + relu -> fp16 plane via packed half2 stores (stride 136 halves)
    int wm = wid >> 1, wn = wid & 1;
    int arow = wm * 32, brow = wn * 64;
    __half2* sh2 = (__half2*)smem;          // 68 half2 per row
    #pragma unroll
    for (int mi = 0; mi < 2; mi++)
        #pragma unroll
        for (int n = 0; n < 8; n++) {
            int r = arow + mi * 16 + (lid >> 2);
            int c = brow + n * 8 + (lid & 3) * 2;
            float v0 = fmaxf(acc[mi][n][0] + bias[c], 0.f);
            float v1 = fmaxf(acc[mi][n][1] + bias[c + 1], 0.f);
            float v2 = fmaxf(acc[mi][n][2] + bias[c], 0.f);
            float v3 = fmaxf(acc[mi][n][3] + bias[c + 1], 0.f);
            sh2[r * 68 + (c >> 1)]       = __halves2half2(__float2half_rn(v0), __float2half_rn(v1));
            sh2[(r + 8) * 68 + (c >> 1)] = __halves2half2(__float2half_rn(v2), __float2half_rn(v3));
        }
    __syncthreads();
    uint4* HF = (uint4*)g_hf;
    #pragma unroll
    for (int i = 0; i < 8; i++) {
        int idx = tid + i * 256;
        int r = idx >> 4, c = idx & 15;
        uint32_t so = (uint32_t)((r * 136 + c * 8) * 2);
        HF[(size_t)(m0 + r) * 256 + (n0 >> 3) + c] = *(uint4*)(smem + so);
    }
}

// ---------------- K4: GEMM2: M64 tile, K-split 2 -> 512 CTAs -------------------
#define AS2 40
#define ST_A (64 * AS2 * 2)            // 5120
#define ST_B (128 * AS2 * 2)           // 10240
#define BUF2 (ST_A + ST_B)             // 15360 per stage
#define G2_SMEM (2 * BUF2 + 512)

__global__ __launch_bounds__(256, 3)
void gemm2_mma() {
    extern __shared__ char smem[];
    uint32_t sb = smem_u32(smem);
    int tid = threadIdx.x, wid = tid >> 5, lid = tid & 31;
    int m0 = blockIdx.x * 64;
    int ksp = blockIdx.y;                  // 0/1 K-split half

    const uint4* srcA = (const uint4*)g_hf  + (size_t)m0 * 256 + ksp * 128;
    const uint4* srcB = (const uint4*)g_w2f + ksp * 128;
    float* dst = ksp ? g_ff1 : g_ff0;

    auto load_chunk = [&](int c, int buf) {
        uint32_t bb = sb + buf * BUF2;
        {
            int r = tid >> 2, cc = tid & 3;  // 64 rows x 4 uint4
            uint32_t so = (uint32_t)((r * AS2 + cc * 8) * 2);
            cp16(bb + so, srcA + (size_t)r * 256 + c * 4 + cc);
        }
        #pragma unroll
        for (int i = 0; i < 2; i++) {        // 128 rows x 4 uint4
            int idx = tid + i * 256;
            int r = idx >> 2, cc = idx & 3;
            uint32_t so = (uint32_t)((r * AS2 + cc * 8) * 2);
            cp16(bb + ST_A + so, srcB + (size_t)r * 256 + c * 4 + cc);
        }
    };

    float acc[2][4][4] = {};
    load_chunk(0, 0);
    CP_COMMIT();

    for (int c = 0; c < 32; c++) {
        if (c + 1 < 32) {
            load_chunk(c + 1, (c + 1) & 1);
            CP_COMMIT();
            cp_wait<1>();
        } else {
            cp_wait<0>();
        }
        __syncthreads();
        uint32_t bb = sb + (c & 1) * BUF2;
        mma_tile64<AS2, 2>(bb, 0, ST_A, acc, wid, lid);
        __syncthreads();
    }

    int wm = wid >> 2, wn = wid & 3;
    int arow = wm * 32, brow = wn * 32;
    #pragma unroll
    for (int mi = 0; mi < 2; mi++)
        #pragma unroll
        for (int n = 0; n < 4; n++) {
            int gr = m0 + arow + mi * 16 + (lid >> 2);
            int cc = brow + n * 8 + (lid & 3) * 2;
            if (cc < DIM) {
                dst[(size_t)gr * DIM + cc]       = acc[mi][n][0];
                dst[(size_t)(gr + 8) * DIM + cc] = acc[mi][n][2];
            }
            if (cc + 1 < DIM) {
                dst[(size_t)gr * DIM + cc + 1]       = acc[mi][n][1];
                dst[(size_t)(gr + 8) * DIM + cc + 1] = acc[mi][n][3];
            }
        }
}

// ---------------- K5: fused LN2 + scoring ------------------------------------
__global__ __launch_bounds__(256, 2)
void ln2_score_tc(const float* __restrict__ ln2_g, const float* __restrict__ ln2_b,
                  const int* __restrict__ items, const float* __restrict__ rec_b,
                  const float* __restrict__ b2, float* __restrict__ out) {
    extern __shared__ char smem[];
    uint32_t sb = smem_u32(smem);
    int tid = threadIdx.x, wid = tid >> 5, lid = tid & 31;
    int m0 = blockIdx.x * 128;
    float* srecb = (float*)(smem + F_T);
    float* sb2   = (float*)(smem + F_T + 512);
    if (tid < KPAD) {
        srecb[tid] = (tid < DIM) ? rec_b[tid] : 0.f;
        sb2[tid]   = (tid < DIM) ? b2[tid]    : 0.f;
    }

    const uint4* B4 = (const uint4*)g_recf;
    #pragma unroll
    for (int i = 0; i < 8; i++) {
        int idx = tid + i * 256;
        int r = idx >> 4, c = idx & 15;
        uint32_t so = (uint32_t)((r * FAS + c * 8) * 2);
        *(uint4*)(smem + F_B + so) = B4[r * 16 + c];
    }
    __syncthreads();

    for (int rr = 0; rr < 16; rr++) {
        int r = wid * 16 + rr;
        float v[4], s = 0.f, sq = 0.f;
        #pragma unroll
        for (int q = 0; q < 4; q++) {
            int t = lid + q * 32;
            v[q] = 0.f;
            if (t < DIM) {
                size_t o = (size_t)(m0 + r) * DIM + t;
                v[q] = g_x1[(size_t)(m0 + r) * KPAD + t]
                     + (g_ff0[o] + g_ff1[o] + sb2[t]);
            }
            s += v[q]; sq += v[q] * v[q];
        }
        #pragma unroll
        for (int off = 16; off; off >>= 1) {
            s  += __shfl_xor_sync(0xffffffffu, s,  off);
            sq += __shfl_xor_sync(0xffffffffu, sq, off);
        }
        float m = s / DIM;
        float inv = rsqrtf(sq / DIM - m * m + EPS);
        #pragma unroll
        for (int q = 0; q < 4; q++) {
            int t = lid + q * 32;
            float o = (t < DIM) ? (v[q] - m) * inv * ln2_g[t] + ln2_b[t] : 0.f;
            *(fp16*)(smem + F_A + ((r * FAS + t) << 1)) = __float2half_rn(o);
        }
    }
    __syncthreads();

    float acc[2][8][4] = {};
    mma_tile1<FAS, 8>(sb, F_A, F_B, acc, wid, lid);
    __syncthreads();

    float* fbuf = (float*)smem;
    int wm = wid >> 1, wn = wid & 1;
    int arow = wm * 32, brow = wn * 64;
    #pragma unroll
    for (int mi = 0; mi < 2; mi++)
        #pragma unroll
        for (int n = 0; n < 8; n++) {
            int r = arow + mi * 16 + (lid >> 2);
            int c = brow + n * 8 + (lid & 3) * 2;
            fbuf[r * 128 + c]           = acc[mi][n][0];
            fbuf[r * 128 + c + 1]       = acc[mi][n][1];
            fbuf[(r + 8) * 128 + c]     = acc[mi][n][2];
            fbuf[(r + 8) * 128 + c + 1] = acc[mi][n][3];
        }
    __syncthreads();

    for (int o = tid; o < 128 * KPRED; o += 256) {
        int r = o / KPRED, k = o - r * KPRED;
        int idx = items[(size_t)(m0 + r) * KPRED + k];
        out[(size_t)(m0 + r) * KPRED + k] = fbuf[r * 128 + idx] + srecb[idx];
    }
}

// ---------------- launch ------------------------------------------------------
extern "C" void kernel_launch(void* const* d_in, const int* in_sizes, int n_in,
                              void* d_out, int out_size) {
    const int*   item_seq   = (const int*)  d_in[0];
    const int*   items_pred = (const int*)  d_in[1];
    const float* item_emb_w = (const float*)d_in[2];
    const float* rec_emb_w  = (const float*)d_in[3];
    const float* rec_b_w    = (const float*)d_in[4];
    const float* in_proj_w  = (const float*)d_in[5];
    const float* in_proj_b  = (const float*)d_in[6];
    const float* out_proj_w = (const float*)d_in[7];
    const float* out_proj_b = (const float*)d_in[8];
    const float* ln1_g      = (const float*)d_in[9];
    const float* ln1_b      = (const float*)d_in[10];
    const float* ln2_g      = (const float*)d_in[11];
    const float* ln2_b      = (const float*)d_in[12];
    const float* ffn_w1     = (const float*)d_in[13];
    const float* ffn_b1     = (const float*)d_in[14];
    const float* ffn_w2     = (const float*)d_in[15];
    const float* ffn_b2     = (const float*)d_in[16];
    float* out = (float*)d_out;

    int B = in_sizes[0] / SEQ_L;

    cudaFuncSetAttribute(attn_ln1_tc,  cudaFuncAttributeMaxDynamicSharedMemorySize, F_SMEM);
    cudaFuncSetAttribute(ln2_score_tc, cudaFuncAttributeMaxDynamicSharedMemorySize, F_SMEM);
    cudaFuncSetAttribute(gemm1_mma, cudaFuncAttributeMaxDynamicSharedMemorySize, G1_SMEM);
    cudaFuncSetAttribute(gemm2_mma, cudaFuncAttributeMaxDynamicSharedMemorySize, G2_SMEM);

    prep_all<<<2176, 256>>>(in_proj_w, in_proj_b, out_proj_w, out_proj_b,
                            rec_emb_w, ffn_w1, ffn_w2);
    embed_sum<<<B, 128>>>(item_seq, item_emb_w);
    attn_ln1_tc<<<B / 128, 256, F_SMEM>>>(ln1_g, ln1_b);
    gemm1_mma<<<dim3(B / 128, FFDIM / 128), 256, G1_SMEM>>>(ffn_b1);
    gemm2_mma<<<dim3(B / 64, 2), 256, G2_SMEM>>>();
    ln2_score_tc<<<B / 128, 256, F_SMEM>>>(ln2_g, ln2_b, items_pred, rec_b_w,
                                           ffn_b2, out);
}

// round 13
// speedup vs baseline: 2.3768x; 1.0828x over previous
#include <cuda_runtime.h>
#include <cuda_fp16.h>
#include <cstdint>

#define SEQ_L 50
#define DIM 100
#define KPAD 128
#define FFDIM 2048
#define KPRED 100
#define EPS 1e-5f
#define BMAX 16384

typedef __half fp16;

// ---------------- scratch (device globals) ---------------------------------
__device__ float g_x  [BMAX * DIM];
__device__ float g_x1 [BMAX * KPAD];
__device__ float g_ff0[BMAX * DIM];
__device__ float g_ff1[BMAX * DIM];
__device__ float g_c  [KPAD];
__device__ fp16  g_Mf  [KPAD * KPAD];
__device__ fp16  g_recf[KPAD * KPAD];
__device__ fp16  g_x1f[BMAX * KPAD];
__device__ fp16  g_w1f[FFDIM * KPAD];
__device__ fp16  g_hf [(size_t)BMAX * FFDIM];
__device__ fp16  g_w2f[KPAD * FFDIM];

// ---------------- helpers ----------------------------------------------------
__device__ __forceinline__ uint32_t smem_u32(const void* p) {
    uint32_t a;
    asm("{ .reg .u64 t; cvta.to.shared.u64 t, %1; cvt.u32.u64 %0, t; }" : "=r"(a) : "l"(p));
    return a;
}
__device__ __forceinline__ void ldsm_x4(uint32_t addr, uint32_t& r0, uint32_t& r1,
                                        uint32_t& r2, uint32_t& r3) {
    asm volatile("ldmatrix.sync.aligned.m8n8.x4.shared.b16 {%0,%1,%2,%3}, [%4];"
                 : "=r"(r0), "=r"(r1), "=r"(r2), "=r"(r3) : "r"(addr));
}
__device__ __forceinline__ void mma_f16(float* d, const uint32_t* a, const uint32_t* b) {
    asm volatile("mma.sync.aligned.m16n8k16.row.col.f32.f16.f16.f32 "
                 "{%0,%1,%2,%3}, {%4,%5,%6,%7}, {%8,%9}, {%0,%1,%2,%3};"
                 : "+f"(d[0]), "+f"(d[1]), "+f"(d[2]), "+f"(d[3])
                 : "r"(a[0]), "r"(a[1]), "r"(a[2]), "r"(a[3]), "r"(b[0]), "r"(b[1]));
}
__device__ __forceinline__ void cp16(uint32_t saddr, const void* g) {
    asm volatile("cp.async.cg.shared.global [%0], [%1], 16;" :: "r"(saddr), "l"(g));
}
#define CP_COMMIT() asm volatile("cp.async.commit_group;" ::: "memory")
template<int N> __device__ __forceinline__ void cp_wait() {
    asm volatile("cp.async.wait_group %0;" :: "n"(N) : "memory");
}

// 128x128 warp-tiled MMA phase (8 warps, warp tile 32x64) — for gemm1
template<int AS, int NKS>
__device__ __forceinline__ void mma_tile1(uint32_t sb, uint32_t oA, uint32_t oB,
                                          float acc[2][8][4], int wid, int lid) {
    int wm = wid >> 1, wn = wid & 1;
    int arow = wm * 32, brow = wn * 64;
    int lr = lid & 15, lc8 = (lid >> 4) << 3;
    #pragma unroll
    for (int ks = 0; ks < NKS; ks++) {
        int k0 = ks * 16;
        uint32_t a[2][4];
        #pragma unroll
        for (int mi = 0; mi < 2; mi++) {
            uint32_t off = (uint32_t)(((arow + mi * 16 + lr) * AS + k0 + lc8) * 2);
            ldsm_x4(sb + oA + off, a[mi][0], a[mi][1], a[mi][2], a[mi][3]);
        }
        uint32_t b[8][2];
        #pragma unroll
        for (int nj = 0; nj < 4; nj++) {
            uint32_t off = (uint32_t)(((brow + nj * 16 + lr) * AS + k0 + lc8) * 2);
            uint32_t r0, r1, r2, r3;
            ldsm_x4(sb + oB + off, r0, r1, r2, r3);
            b[nj * 2][0] = r0; b[nj * 2 + 1][0] = r1;
            b[nj * 2][1] = r2; b[nj * 2 + 1][1] = r3;
        }
        #pragma unroll
        for (int mi = 0; mi < 2; mi++)
            #pragma unroll
            for (int n = 0; n < 8; n++)
                mma_f16(acc[mi][n], a[mi], b[n]);
    }
}

// 64x128 warp-tiled MMA phase (8 warps, warp tile 32x32)
template<int AS, int NKS>
__device__ __forceinline__ void mma_tile64(uint32_t sb, uint32_t oA, uint32_t oB,
                                           float acc[2][4][4], int wid, int lid) {
    int wm = wid >> 2, wn = wid & 3;
    int arow = wm * 32, brow = wn * 32;
    int lr = lid & 15, lc8 = (lid >> 4) << 3;
    #pragma unroll
    for (int ks = 0; ks < NKS; ks++) {
        int k0 = ks * 16;
        uint32_t a[2][4];
        #pragma unroll
        for (int mi = 0; mi < 2; mi++) {
            uint32_t off = (uint32_t)(((arow + mi * 16 + lr) * AS + k0 + lc8) * 2);
            ldsm_x4(sb + oA + off, a[mi][0], a[mi][1], a[mi][2], a[mi][3]);
        }
        uint32_t b[4][2];
        #pragma unroll
        for (int nj = 0; nj < 2; nj++) {
            uint32_t off = (uint32_t)(((brow + nj * 16 + lr) * AS + k0 + lc8) * 2);
            uint32_t r0, r1, r2, r3;
            ldsm_x4(sb + oB + off, r0, r1, r2, r3);
            b[nj * 2][0] = r0; b[nj * 2 + 1][0] = r1;
            b[nj * 2][1] = r2; b[nj * 2 + 1][1] = r3;
        }
        #pragma unroll
        for (int mi = 0; mi < 2; mi++)
            #pragma unroll
            for (int n = 0; n < 4; n++)
                mma_f16(acc[mi][n], a[mi], b[n]);
    }
}

// ---------------- K0: fused prep ---------------------------------------------
__global__ void prep_all(const float* __restrict__ in_proj_w,
                         const float* __restrict__ in_proj_b,
                         const float* __restrict__ out_proj_w,
                         const float* __restrict__ out_proj_b,
                         const float* __restrict__ rec_emb,
                         const float* __restrict__ w1,
                         const float* __restrict__ w2) {
    int bid = blockIdx.x, tid = threadIdx.x;
    if (bid < 64) {
        int i = bid * 2 + (tid >> 7);
        int j = tid & 127;
        const float* Wv = in_proj_w + 2 * DIM * DIM;
        const float* bv = in_proj_b + 2 * DIM;
        float mv = 0.f;
        if (i < DIM && j < DIM) {
            #pragma unroll 4
            for (int k = 0; k < DIM; k++)
                mv += out_proj_w[i * DIM + k] * Wv[k * DIM + j];
        }
        g_Mf[i * KPAD + j] = __float2half_rn(mv);
        if (j == 0) {
            float s = 0.f;
            if (i < DIM) {
                s = out_proj_b[i];
                for (int k = 0; k < DIM; k++)
                    s += out_proj_w[i * DIM + k] * bv[k];
            }
            g_c[i] = s;
        }
    } else if (bid < 128) {
        int idx = (bid - 64) * 256 + tid;
        int n = idx >> 7, k = idx & 127;
        float v = (n < DIM && k < DIM) ? rec_emb[n * DIM + k] : 0.f;
        g_recf[idx] = __float2half_rn(v);
    } else if (bid < 128 + 1024) {
        int idx = (bid - 128) * 256 + tid;
        int n = idx >> 7, k = idx & 127;
        float v = (k < DIM) ? w1[n * DIM + k] : 0.f;
        g_w1f[idx] = __float2half_rn(v);
    } else {
        int idx = (bid - 1152) * 256 + tid;
        int n = idx >> 11, k = idx & 2047;
        float v = (n < DIM) ? w2[n * FFDIM + k] : 0.f;
        g_w2f[idx] = __float2half_rn(v);
    }
}

// ---------------- K1: embedding gather-sum ------------------------------------
__global__ void embed_sum(const int* __restrict__ seq,
                          const float* __restrict__ emb) {
    int b = blockIdx.x;
    __shared__ int s_idx[SEQ_L];
    int t = threadIdx.x;
    if (t < SEQ_L) s_idx[t] = seq[b * SEQ_L + t];
    __syncthreads();
    if (t < DIM) {
        float acc = 0.f;
        #pragma unroll 5
        for (int l = 0; l < SEQ_L; l++)
            acc += emb[(size_t)s_idx[l] * DIM + t];
        g_x[b * DIM + t] = acc;
    }
}

// ---------------- M64 fused-tile smem layout (attn_ln1 / ln2_score) -----------
#define FAS 136
#define A64_SZ (64 * FAS * 2)          // 17408
#define B128_SZ (128 * FAS * 2)        // 34816
#define F2_A 0
#define F2_B A64_SZ
#define F2_T (A64_SZ + B128_SZ)        // 52224
#define F2_SMEM (F2_T + 1024)          // 53248

// ---------------- K2: fused attn + LN1 (M-tile 64, 256 CTAs) ------------------
__global__ __launch_bounds__(256, 3)
void attn_ln1_tc(const float* __restrict__ ln1_g, const float* __restrict__ ln1_b) {
    extern __shared__ char smem[];
    uint32_t sb = smem_u32(smem);
    int tid = threadIdx.x, wid = tid >> 5, lid = tid & 31;
    int m0 = blockIdx.x * 64;
    float* cvec = (float*)(smem + F2_T);
    if (tid < KPAD) cvec[tid] = g_c[tid];

    // A plane: 64 rows fp16 of x
    for (int idx = tid; idx < 64 * 128; idx += 256) {
        int r = idx >> 7, j = idx & 127;
        float v = (j < DIM) ? g_x[(size_t)(m0 + r) * DIM + j] : 0.f;
        *(fp16*)(smem + F2_A + ((r * FAS + j) << 1)) = __float2half_rn(v);
    }
    // B plane (g_Mf, full 128 rows)
    const uint4* B4 = (const uint4*)g_Mf;
    #pragma unroll
    for (int i = 0; i < 8; i++) {
        int idx = tid + i * 256;
        int r = idx >> 4, c = idx & 15;
        uint32_t so = (uint32_t)((r * FAS + c * 8) * 2);
        *(uint4*)(smem + F2_B + so) = B4[r * 16 + c];
    }
    __syncthreads();

    float acc[2][4][4] = {};
    mma_tile64<FAS, 8>(sb, F2_A, F2_B, acc, wid, lid);
    __syncthreads();

    // overlay: y = x + attn + c, fp32 stride 132 (64 rows = 33.8KB over planes)
    float* ybuf = (float*)smem;
    int wm = wid >> 2, wn = wid & 3;
    int arow = wm * 32, brow = wn * 32;
    #pragma unroll
    for (int mi = 0; mi < 2; mi++)
        #pragma unroll
        for (int n = 0; n < 4; n++) {
            int r = arow + mi * 16 + (lid >> 2);
            int c = brow + n * 8 + (lid & 3) * 2;
            float x0 = (c     < DIM) ? g_x[(size_t)(m0 + r) * DIM + c]     : 0.f;
            float x1v= (c + 1 < DIM) ? g_x[(size_t)(m0 + r) * DIM + c + 1] : 0.f;
            float x2 = (c     < DIM) ? g_x[(size_t)(m0 + r + 8) * DIM + c]     : 0.f;
            float x3 = (c + 1 < DIM) ? g_x[(size_t)(m0 + r + 8) * DIM + c + 1] : 0.f;
            ybuf[r * 132 + c]           = acc[mi][n][0] + x0  + cvec[c];
            ybuf[r * 132 + c + 1]       = acc[mi][n][1] + x1v + cvec[c + 1];
            ybuf[(r + 8) * 132 + c]     = acc[mi][n][2] + x2  + cvec[c];
            ybuf[(r + 8) * 132 + c + 1] = acc[mi][n][3] + x3  + cvec[c + 1];
        }
    __syncthreads();

    // LN: 8 rows per warp
    for (int rr = 0; rr < 8; rr++) {
        int r = wid * 8 + rr;
        float v[4], s = 0.f, sq = 0.f;
        #pragma unroll
        for (int q = 0; q < 4; q++) {
            int t = lid + q * 32;
            v[q] = (t < DIM) ? ybuf[r * 132 + t] : 0.f;
            s += v[q]; sq += v[q] * v[q];
        }
        #pragma unroll
        for (int off = 16; off; off >>= 1) {
            s  += __shfl_xor_sync(0xffffffffu, s,  off);
            sq += __shfl_xor_sync(0xffffffffu, sq, off);
        }
        float m = s / DIM;
        float inv = rsqrtf(sq / DIM - m * m + EPS);
        #pragma unroll
        for (int q = 0; q < 4; q++) {
            int t = lid + q * 32;
            float o = (t < DIM) ? (v[q] - m) * inv * ln1_g[t] + ln1_b[t] : 0.f;
            g_x1 [(size_t)(m0 + r) * KPAD + t] = o;
            g_x1f[(size_t)(m0 + r) * KPAD + t] = __float2half_rn(o);
        }
    }
}

// ---------------- K3: GEMM1: cp.async double-buffered K=64 stages -------------
#define AS1 72
#define PA1 (128 * AS1 * 2)
#define STG1 (2 * PA1)
#define S1_BIAS (2 * STG1)
#define G1_SMEM (2 * STG1 + 512)

__global__ __launch_bounds__(256, 2)
void gemm1_mma(const float* __restrict__ b1) {
    extern __shared__ char smem[];
    uint32_t sb = smem_u32(smem);
    int tid = threadIdx.x, wid = tid >> 5, lid = tid & 31;
    int m0 = blockIdx.x * 128, n0 = blockIdx.y * 128;
    float* bias = (float*)(smem + S1_BIAS);
    if (tid < 128) bias[tid] = b1[n0 + tid];

    const uint4* A4 = (const uint4*)g_x1f + (size_t)m0 * 16;
    const uint4* B4 = (const uint4*)g_w1f + (size_t)n0 * 16;

    auto load_stage = [&](int kh, int buf) {
        uint32_t bb = sb + buf * STG1;
        #pragma unroll
        for (int i = 0; i < 4; i++) {
            int idx = tid + i * 256;
            int r = idx >> 3, c = idx & 7;
            uint32_t so = (uint32_t)((r * AS1 + c * 8) * 2);
            cp16(bb + so,       A4 + (size_t)r * 16 + kh * 8 + c);
            cp16(bb + PA1 + so, B4 + (size_t)r * 16 + kh * 8 + c);
        }
    };

    float acc[2][8][4] = {};
    load_stage(0, 0); CP_COMMIT();
    load_stage(1, 1); CP_COMMIT();
    cp_wait<1>();
    __syncthreads();
    mma_tile1<AS1, 4>(sb, 0, PA1, acc, wid, lid);
    cp_wait<0>();
    __syncthreads();
    mma_tile1<AS1, 4>(sb, STG1, STG1 + PA1, acc, wid, lid);
    __syncthreads();

    int wm = wid >> 1, wn = wid & 1;
    int arow = wm * 32, brow = wn * 64;
    __half2* sh2 = (__half2*)smem;
    #pragma unroll
    for (int mi = 0; mi < 2; mi++)
        #pragma unroll
        for (int n = 0; n < 8; n++) {
            int r = arow + mi * 16 + (lid >> 2);
            int c = brow + n * 8 + (lid & 3) * 2;
            float v0 = fmaxf(acc[mi][n][0] + bias[c], 0.f);
            float v1 = fmaxf(acc[mi][n][1] + bias[c + 1], 0.f);
            float v2 = fmaxf(acc[mi][n][2] + bias[c], 0.f);
            float v3 = fmaxf(acc[mi][n][3] + bias[c + 1], 0.f);
            sh2[r * 68 + (c >> 1)]       = __halves2half2(__float2half_rn(v0), __float2half_rn(v1));
            sh2[(r + 8) * 68 + (c >> 1)] = __halves2half2(__float2half_rn(v2), __float2half_rn(v3));
        }
    __syncthreads();
    uint4* HF = (uint4*)g_hf;
    #pragma unroll
    for (int i = 0; i < 8; i++) {
        int idx = tid + i * 256;
        int r = idx >> 4, c = idx & 15;
        uint32_t so = (uint32_t)((r * 136 + c * 8) * 2);
        HF[(size_t)(m0 + r) * 256 + (n0 >> 3) + c] = *(uint4*)(smem + so);
    }
}

// ---------------- K4: GEMM2: M64, K-split 2, 4-stage pipeline ------------------
#define AS2 40
#define ST_A (64 * AS2 * 2)            // 5120
#define ST_B (128 * AS2 * 2)           // 10240
#define BUF2 (ST_A + ST_B)             // 15360 per stage
#define G2_SMEM (4 * BUF2 + 512)       // 61952

__global__ __launch_bounds__(256, 3)
void gemm2_mma() {
    extern __shared__ char smem[];
    uint32_t sb = smem_u32(smem);
    int tid = threadIdx.x, wid = tid >> 5, lid = tid & 31;
    int m0 = blockIdx.x * 64;
    int ksp = blockIdx.y;

    const uint4* srcA = (const uint4*)g_hf  + (size_t)m0 * 256 + ksp * 128;
    const uint4* srcB = (const uint4*)g_w2f + ksp * 128;
    float* dst = ksp ? g_ff1 : g_ff0;

    auto load_chunk = [&](int c, int buf) {
        uint32_t bb = sb + buf * BUF2;
        {
            int r = tid >> 2, cc = tid & 3;
            uint32_t so = (uint32_t)((r * AS2 + cc * 8) * 2);
            cp16(bb + so, srcA + (size_t)r * 256 + c * 4 + cc);
        }
        #pragma unroll
        for (int i = 0; i < 2; i++) {
            int idx = tid + i * 256;
            int r = idx >> 2, cc = idx & 3;
            uint32_t so = (uint32_t)((r * AS2 + cc * 8) * 2);
            cp16(bb + ST_A + so, srcB + (size_t)r * 256 + c * 4 + cc);
        }
    };

    float acc[2][4][4] = {};
    load_chunk(0, 0); CP_COMMIT();
    load_chunk(1, 1); CP_COMMIT();
    load_chunk(2, 2); CP_COMMIT();

    for (int c = 0; c < 32; c++) {
        cp_wait<2>();
        __syncthreads();
        uint32_t bb = sb + (c & 3) * BUF2;
        mma_tile64<AS2, 2>(bb, 0, ST_A, acc, wid, lid);
        __syncthreads();
        if (c + 3 < 32) {
            load_chunk(c + 3, (c + 3) & 3);
            CP_COMMIT();
        } else {
            CP_COMMIT();   // keep group count aligned for cp_wait<2>
        }
    }

    int wm = wid >> 2, wn = wid & 3;
    int arow = wm * 32, brow = wn * 32;
    #pragma unroll
    for (int mi = 0; mi < 2; mi++)
        #pragma unroll
        for (int n = 0; n < 4; n++) {
            int gr = m0 + arow + mi * 16 + (lid >> 2);
            int cc = brow + n * 8 + (lid & 3) * 2;
            if (cc < DIM) {
                dst[(size_t)gr * DIM + cc]       = acc[mi][n][0];
                dst[(size_t)(gr + 8) * DIM + cc] = acc[mi][n][2];
            }
            if (cc + 1 < DIM) {
                dst[(size_t)gr * DIM + cc + 1]       = acc[mi][n][1];
                dst[(size_t)(gr + 8) * DIM + cc + 1] = acc[mi][n][3];
            }
        }
}

// ---------------- K5: fused LN2 + scoring (M-tile 64, 256 CTAs) ----------------
__global__ __launch_bounds__(256, 3)
void ln2_score_tc(const float* __restrict__ ln2_g, const float* __restrict__ ln2_b,
                  const int* __restrict__ items, const float* __restrict__ rec_b,
                  const float* __restrict__ b2, float* __restrict__ out) {
    extern __shared__ char smem[];
    uint32_t sb = smem_u32(smem);
    int tid = threadIdx.x, wid = tid >> 5, lid = tid & 31;
    int m0 = blockIdx.x * 64;
    float* srecb = (float*)(smem + F2_T);
    float* sb2   = (float*)(smem + F2_T + 512);
    if (tid < KPAD) {
        srecb[tid] = (tid < DIM) ? rec_b[tid] : 0.f;
        sb2[tid]   = (tid < DIM) ? b2[tid]    : 0.f;
    }

    const uint4* B4 = (const uint4*)g_recf;
    #pragma unroll
    for (int i = 0; i < 8; i++) {
        int idx = tid + i * 256;
        int r = idx >> 4, c = idx & 15;
        uint32_t so = (uint32_t)((r * FAS + c * 8) * 2);
        *(uint4*)(smem + F2_B + so) = B4[r * 16 + c];
    }
    __syncthreads();

    // LN: 8 rows per warp, read y = x1 + (ff0+ff1+b2) from global
    for (int rr = 0; rr < 8; rr++) {
        int r = wid * 8 + rr;
        float v[4], s = 0.f, sq = 0.f;
        #pragma unroll
        for (int q = 0; q < 4; q++) {
            int t = lid + q * 32;
            v[q] = 0.f;
            if (t < DIM) {
                size_t o = (size_t)(m0 + r) * DIM + t;
                v[q] = g_x1[(size_t)(m0 + r) * KPAD + t]
                     + (g_ff0[o] + g_ff1[o] + sb2[t]);
            }
            s += v[q]; sq += v[q] * v[q];
        }
        #pragma unroll
        for (int off = 16; off; off >>= 1) {
            s  += __shfl_xor_sync(0xffffffffu, s,  off);
            sq += __shfl_xor_sync(0xffffffffu, sq, off);
        }
        float m = s / DIM;
        float inv = rsqrtf(sq / DIM - m * m + EPS);
        #pragma unroll
        for (int q = 0; q < 4; q++) {
            int t = lid + q * 32;
            float o = (t < DIM) ? (v[q] - m) * inv * ln2_g[t] + ln2_b[t] : 0.f;
            *(fp16*)(smem + F2_A + ((r * FAS + t) << 1)) = __float2half_rn(o);
        }
    }
    __syncthreads();

    float acc[2][4][4] = {};
    mma_tile64<FAS, 8>(sb, F2_A, F2_B, acc, wid, lid);
    __syncthreads();

    // overlay P fp32 (64 x 128, stride 128 -> 32KB)
    float* fbuf = (float*)smem;
    int wm = wid >> 2, wn = wid & 3;
    int arow = wm * 32, brow = wn * 32;
    #pragma unroll
    for (int mi = 0; mi < 2; mi++)
        #pragma unroll
        for (int n = 0; n < 4; n++) {
            int r = arow + mi * 16 + (lid >> 2);
            int c = brow + n * 8 + (lid & 3) * 2;
            fbuf[r * 128 + c]           = acc[mi][n][0];
            fbuf[r * 128 + c + 1]       = acc[mi][n][1];
            fbuf[(r + 8) * 128 + c]     = acc[mi][n][2];
            fbuf[(r + 8) * 128 + c + 1] = acc[mi][n][3];
        }
    __syncthreads();

    for (int o = tid; o < 64 * KPRED; o += 256) {
        int r = o / KPRED, k = o - r * KPRED;
        int idx = items[(size_t)(m0 + r) * KPRED + k];
        out[(size_t)(m0 + r) * KPRED + k] = fbuf[r * 128 + idx] + srecb[idx];
    }
}

// ---------------- launch ------------------------------------------------------
extern "C" void kernel_launch(void* const* d_in, const int* in_sizes, int n_in,
                              void* d_out, int out_size) {
    const int*   item_seq   = (const int*)  d_in[0];
    const int*   items_pred = (const int*)  d_in[1];
    const float* item_emb_w = (const float*)d_in[2];
    const float* rec_emb_w  = (const float*)d_in[3];
    const float* rec_b_w    = (const float*)d_in[4];
    const float* in_proj_w  = (const float*)d_in[5];
    const float* in_proj_b  = (const float*)d_in[6];
    const float* out_proj_w = (const float*)d_in[7];
    const float* out_proj_b = (const float*)d_in[8];
    const float* ln1_g      = (const float*)d_in[9];
    const float* ln1_b      = (const float*)d_in[10];
    const float* ln2_g      = (const float*)d_in[11];
    const float* ln2_b      = (const float*)d_in[12];
    const float* ffn_w1     = (const float*)d_in[13];
    const float* ffn_b1     = (const float*)d_in[14];
    const float* ffn_w2     = (const float*)d_in[15];
    const float* ffn_b2     = (const float*)d_in[16];
    float* out = (float*)d_out;

    int B = in_sizes[0] / SEQ_L;

    cudaFuncSetAttribute(attn_ln1_tc,  cudaFuncAttributeMaxDynamicSharedMemorySize, F2_SMEM);
    cudaFuncSetAttribute(ln2_score_tc, cudaFuncAttributeMaxDynamicSharedMemorySize, F2_SMEM);
    cudaFuncSetAttribute(gemm1_mma, cudaFuncAttributeMaxDynamicSharedMemorySize, G1_SMEM);
    cudaFuncSetAttribute(gemm2_mma, cudaFuncAttributeMaxDynamicSharedMemorySize, G2_SMEM);

    prep_all<<<2176, 256>>>(in_proj_w, in_proj_b, out_proj_w, out_proj_b,
                            rec_emb_w, ffn_w1, ffn_w2);
    embed_sum<<<B, 128>>>(item_seq, item_emb_w);
    attn_ln1_tc<<<B / 64, 256, F2_SMEM>>>(ln1_g, ln1_b);
    gemm1_mma<<<dim3(B / 128, FFDIM / 128), 256, G1_SMEM>>>(ffn_b1);
    gemm2_mma<<<dim3(B / 64, 2), 256, G2_SMEM>>>();
    ln2_score_tc<<<B / 64, 256, F2_SMEM>>>(ln2_g, ln2_b, items_pred, rec_b_w,
                                           ffn_b2, out);
}

// round 14
// speedup vs baseline: 2.4711x; 1.0397x over previous
#include <cuda_runtime.h>
#include <cuda_fp16.h>
#include <cstdint>

#define SEQ_L 50
#define DIM 100
#define KPAD 128
#define FFDIM 2048
#define KPRED 100
#define EPS 1e-5f
#define BMAX 16384

typedef __half fp16;

// ---------------- scratch (device globals) ---------------------------------
__device__ float g_x  [BMAX * DIM];
__device__ float g_x1 [BMAX * KPAD];
__device__ float g_ff0[BMAX * DIM];
__device__ float g_ff1[BMAX * DIM];
__device__ float g_c  [KPAD];
__device__ fp16  g_Mf  [KPAD * KPAD];
__device__ fp16  g_recf[KPAD * KPAD];
__device__ fp16  g_x1f[BMAX * KPAD];
__device__ fp16  g_w1f[FFDIM * KPAD];
__device__ fp16  g_hf [(size_t)BMAX * FFDIM];
__device__ fp16  g_w2f[KPAD * FFDIM];

// ---------------- helpers ----------------------------------------------------
__device__ __forceinline__ uint32_t smem_u32(const void* p) {
    uint32_t a;
    asm("{ .reg .u64 t; cvta.to.shared.u64 t, %1; cvt.u32.u64 %0, t; }" : "=r"(a) : "l"(p));
    return a;
}
__device__ __forceinline__ void ldsm_x4(uint32_t addr, uint32_t& r0, uint32_t& r1,
                                        uint32_t& r2, uint32_t& r3) {
    asm volatile("ldmatrix.sync.aligned.m8n8.x4.shared.b16 {%0,%1,%2,%3}, [%4];"
                 : "=r"(r0), "=r"(r1), "=r"(r2), "=r"(r3) : "r"(addr));
}
__device__ __forceinline__ void mma_f16(float* d, const uint32_t* a, const uint32_t* b) {
    asm volatile("mma.sync.aligned.m16n8k16.row.col.f32.f16.f16.f32 "
                 "{%0,%1,%2,%3}, {%4,%5,%6,%7}, {%8,%9}, {%0,%1,%2,%3};"
                 : "+f"(d[0]), "+f"(d[1]), "+f"(d[2]), "+f"(d[3])
                 : "r"(a[0]), "r"(a[1]), "r"(a[2]), "r"(a[3]), "r"(b[0]), "r"(b[1]));
}
__device__ __forceinline__ void cp16(uint32_t saddr, const void* g) {
    asm volatile("cp.async.cg.shared.global [%0], [%1], 16;" :: "r"(saddr), "l"(g));
}
#define CP_COMMIT() asm volatile("cp.async.commit_group;" ::: "memory")
template<int N> __device__ __forceinline__ void cp_wait() {
    asm volatile("cp.async.wait_group %0;" :: "n"(N) : "memory");
}

// M128 x N64 warp-tiled MMA phase (8 warps as 4m x 2n, warp tile 32x32) — gemm1
template<int AS, int NKS>
__device__ __forceinline__ void mma_m128n64(uint32_t sb, uint32_t oA, uint32_t oB,
                                            float acc[2][4][4], int wid, int lid) {
    int arow = (wid >> 1) * 32, brow = (wid & 1) * 32;
    int lr = lid & 15, lc8 = (lid >> 4) << 3;
    #pragma unroll
    for (int ks = 0; ks < NKS; ks++) {
        int k0 = ks * 16;
        uint32_t a[2][4];
        #pragma unroll
        for (int mi = 0; mi < 2; mi++) {
            uint32_t off = (uint32_t)(((arow + mi * 16 + lr) * AS + k0 + lc8) * 2);
            ldsm_x4(sb + oA + off, a[mi][0], a[mi][1], a[mi][2], a[mi][3]);
        }
        uint32_t b[4][2];
        #pragma unroll
        for (int nj = 0; nj < 2; nj++) {
            uint32_t off = (uint32_t)(((brow + nj * 16 + lr) * AS + k0 + lc8) * 2);
            uint32_t r0, r1, r2, r3;
            ldsm_x4(sb + oB + off, r0, r1, r2, r3);
            b[nj * 2][0] = r0; b[nj * 2 + 1][0] = r1;
            b[nj * 2][1] = r2; b[nj * 2 + 1][1] = r3;
        }
        #pragma unroll
        for (int mi = 0; mi < 2; mi++)
            #pragma unroll
            for (int n = 0; n < 4; n++)
                mma_f16(acc[mi][n], a[mi], b[n]);
    }
}

// M64 x N128 warp-tiled MMA phase (8 warps as 2m x 4n, warp tile 32x32)
template<int AS, int NKS>
__device__ __forceinline__ void mma_tile64(uint32_t sb, uint32_t oA, uint32_t oB,
                                           float acc[2][4][4], int wid, int lid) {
    int wm = wid >> 2, wn = wid & 3;
    int arow = wm * 32, brow = wn * 32;
    int lr = lid & 15, lc8 = (lid >> 4) << 3;
    #pragma unroll
    for (int ks = 0; ks < NKS; ks++) {
        int k0 = ks * 16;
        uint32_t a[2][4];
        #pragma unroll
        for (int mi = 0; mi < 2; mi++) {
            uint32_t off = (uint32_t)(((arow + mi * 16 + lr) * AS + k0 + lc8) * 2);
            ldsm_x4(sb + oA + off, a[mi][0], a[mi][1], a[mi][2], a[mi][3]);
        }
        uint32_t b[4][2];
        #pragma unroll
        for (int nj = 0; nj < 2; nj++) {
            uint32_t off = (uint32_t)(((brow + nj * 16 + lr) * AS + k0 + lc8) * 2);
            uint32_t r0, r1, r2, r3;
            ldsm_x4(sb + oB + off, r0, r1, r2, r3);
            b[nj * 2][0] = r0; b[nj * 2 + 1][0] = r1;
            b[nj * 2][1] = r2; b[nj * 2 + 1][1] = r3;
        }
        #pragma unroll
        for (int mi = 0; mi < 2; mi++)
            #pragma unroll
            for (int n = 0; n < 4; n++)
                mma_f16(acc[mi][n], a[mi], b[n]);
    }
}

// ---------------- K0: merged embed gather + prep -------------------------------
// blocks [0, 8192): embedding gather (2 rows/block); [8192, 10368): weight prep
__global__ void embed_prep(const int* __restrict__ seq,
                           const float* __restrict__ emb,
                           const float* __restrict__ in_proj_w,
                           const float* __restrict__ in_proj_b,
                           const float* __restrict__ out_proj_w,
                           const float* __restrict__ out_proj_b,
                           const float* __restrict__ rec_emb,
                           const float* __restrict__ w1,
                           const float* __restrict__ w2) {
    int bid = blockIdx.x, tid = threadIdx.x;
    if (bid < 8192) {
        __shared__ int s_idx[2 * SEQ_L];
        int half = tid >> 7;           // 0/1
        int t = tid & 127;
        int b = bid * 2 + half;
        if (t < SEQ_L) s_idx[half * SEQ_L + t] = seq[b * SEQ_L + t];
        __syncthreads();
        if (t < DIM) {
            float acc = 0.f;
            #pragma unroll 5
            for (int l = 0; l < SEQ_L; l++)
                acc += emb[(size_t)s_idx[half * SEQ_L + l] * DIM + t];
            g_x[b * DIM + t] = acc;
        }
        return;
    }
    int pid = bid - 8192;
    if (pid < 64) {
        int i = pid * 2 + (tid >> 7);
        int j = tid & 127;
        const float* Wv = in_proj_w + 2 * DIM * DIM;
        const float* bv = in_proj_b + 2 * DIM;
        float mv = 0.f;
        if (i < DIM && j < DIM) {
            #pragma unroll 4
            for (int k = 0; k < DIM; k++)
                mv += out_proj_w[i * DIM + k] * Wv[k * DIM + j];
        }
        g_Mf[i * KPAD + j] = __float2half_rn(mv);
        if (j == 0) {
            float s = 0.f;
            if (i < DIM) {
                s = out_proj_b[i];
                for (int k = 0; k < DIM; k++)
                    s += out_proj_w[i * DIM + k] * bv[k];
            }
            g_c[i] = s;
        }
    } else if (pid < 128) {
        int idx = (pid - 64) * 256 + tid;
        int n = idx >> 7, k = idx & 127;
        float v = (n < DIM && k < DIM) ? rec_emb[n * DIM + k] : 0.f;
        g_recf[idx] = __float2half_rn(v);
    } else if (pid < 128 + 1024) {
        int idx = (pid - 128) * 256 + tid;
        int n = idx >> 7, k = idx & 127;
        float v = (k < DIM) ? w1[n * DIM + k] : 0.f;
        g_w1f[idx] = __float2half_rn(v);
    } else {
        int idx = (pid - 1152) * 256 + tid;
        int n = idx >> 11, k = idx & 2047;
        float v = (n < DIM) ? w2[n * FFDIM + k] : 0.f;
        g_w2f[idx] = __float2half_rn(v);
    }
}

// ---------------- M64 fused-tile smem layout (attn_ln1 / ln2_score) -----------
#define FAS 136
#define A64_SZ (64 * FAS * 2)          // 17408
#define B128_SZ (128 * FAS * 2)        // 34816
#define F2_A 0
#define F2_B A64_SZ
#define F2_T (A64_SZ + B128_SZ)        // 52224
#define F2_SMEM (F2_T + 1024)          // 53248

// ---------------- K2: fused attn + LN1 (M-tile 64, 256 CTAs) ------------------
__global__ __launch_bounds__(256, 3)
void attn_ln1_tc(const float* __restrict__ ln1_g, const float* __restrict__ ln1_b) {
    extern __shared__ char smem[];
    uint32_t sb = smem_u32(smem);
    int tid = threadIdx.x, wid = tid >> 5, lid = tid & 31;
    int m0 = blockIdx.x * 64;
    float* cvec = (float*)(smem + F2_T);
    if (tid < KPAD) cvec[tid] = g_c[tid];

    for (int idx = tid; idx < 64 * 128; idx += 256) {
        int r = idx >> 7, j = idx & 127;
        float v = (j < DIM) ? g_x[(size_t)(m0 + r) * DIM + j] : 0.f;
        *(fp16*)(smem + F2_A + ((r * FAS + j) << 1)) = __float2half_rn(v);
    }
    const uint4* B4 = (const uint4*)g_Mf;
    #pragma unroll
    for (int i = 0; i < 8; i++) {
        int idx = tid + i * 256;
        int r = idx >> 4, c = idx & 15;
        uint32_t so = (uint32_t)((r * FAS + c * 8) * 2);
        *(uint4*)(smem + F2_B + so) = B4[r * 16 + c];
    }
    __syncthreads();

    float acc[2][4][4] = {};
    mma_tile64<FAS, 8>(sb, F2_A, F2_B, acc, wid, lid);
    __syncthreads();

    float* ybuf = (float*)smem;            // overlay, stride 132
    int wm = wid >> 2, wn = wid & 3;
    int arow = wm * 32, brow = wn * 32;
    #pragma unroll
    for (int mi = 0; mi < 2; mi++)
        #pragma unroll
        for (int n = 0; n < 4; n++) {
            int r = arow + mi * 16 + (lid >> 2);
            int c = brow + n * 8 + (lid & 3) * 2;
            float x0 = (c     < DIM) ? g_x[(size_t)(m0 + r) * DIM + c]     : 0.f;
            float x1v= (c + 1 < DIM) ? g_x[(size_t)(m0 + r) * DIM + c + 1] : 0.f;
            float x2 = (c     < DIM) ? g_x[(size_t)(m0 + r + 8) * DIM + c]     : 0.f;
            float x3 = (c + 1 < DIM) ? g_x[(size_t)(m0 + r + 8) * DIM + c + 1] : 0.f;
            ybuf[r * 132 + c]           = acc[mi][n][0] + x0  + cvec[c];
            ybuf[r * 132 + c + 1]       = acc[mi][n][1] + x1v + cvec[c + 1];
            ybuf[(r + 8) * 132 + c]     = acc[mi][n][2] + x2  + cvec[c];
            ybuf[(r + 8) * 132 + c + 1] = acc[mi][n][3] + x3  + cvec[c + 1];
        }
    __syncthreads();

    for (int rr = 0; rr < 8; rr++) {
        int r = wid * 8 + rr;
        float v[4], s = 0.f, sq = 0.f;
        #pragma unroll
        for (int q = 0; q < 4; q++) {
            int t = lid + q * 32;
            v[q] = (t < DIM) ? ybuf[r * 132 + t] : 0.f;
            s += v[q]; sq += v[q] * v[q];
        }
        #pragma unroll
        for (int off = 16; off; off >>= 1) {
            s  += __shfl_xor_sync(0xffffffffu, s,  off);
            sq += __shfl_xor_sync(0xffffffffu, sq, off);
        }
        float m = s / DIM;
        float inv = rsqrtf(sq / DIM - m * m + EPS);
        #pragma unroll
        for (int q = 0; q < 4; q++) {
            int t = lid + q * 32;
            float o = (t < DIM) ? (v[q] - m) * inv * ln1_g[t] + ln1_b[t] : 0.f;
            g_x1 [(size_t)(m0 + r) * KPAD + t] = o;
            g_x1f[(size_t)(m0 + r) * KPAD + t] = __float2half_rn(o);
        }
    }
}

// ---------------- K3: GEMM1: tile 128x64, occ 3, cp.async 2-stage --------------
#define AS1 72
#define PA1 (128 * AS1 * 2)            // 18432 A plane
#define PB1 (64 * AS1 * 2)             // 9216  B plane
#define STG1 (PA1 + PB1)               // 27648 per stage
#define S1_BIAS (2 * STG1)             // 55296
#define G1_SMEM (2 * STG1 + 512)

__global__ __launch_bounds__(256, 3)
void gemm1_mma(const float* __restrict__ b1) {
    extern __shared__ char smem[];
    uint32_t sb = smem_u32(smem);
    int tid = threadIdx.x, wid = tid >> 5, lid = tid & 31;
    int m0 = blockIdx.x * 128, n0 = blockIdx.y * 64;
    float* bias = (float*)(smem + S1_BIAS);
    if (tid < 64) bias[tid] = b1[n0 + tid];

    const uint4* A4 = (const uint4*)g_x1f + (size_t)m0 * 16;
    const uint4* B4 = (const uint4*)g_w1f + (size_t)n0 * 16;

    auto load_stage = [&](int kh, int buf) {
        uint32_t bb = sb + buf * STG1;
        #pragma unroll
        for (int i = 0; i < 4; i++) {       // A: 128 rows x 8 uint4
            int idx = tid + i * 256;
            int r = idx >> 3, c = idx & 7;
            uint32_t so = (uint32_t)((r * AS1 + c * 8) * 2);
            cp16(bb + so, A4 + (size_t)r * 16 + kh * 8 + c);
        }
        #pragma unroll
        for (int i = 0; i < 2; i++) {       // B: 64 rows x 8 uint4
            int idx = tid + i * 256;
            int r = idx >> 3, c = idx & 7;
            uint32_t so = (uint32_t)((r * AS1 + c * 8) * 2);
            cp16(bb + PA1 + so, B4 + (size_t)r * 16 + kh * 8 + c);
        }
    };

    float acc[2][4][4] = {};
    load_stage(0, 0); CP_COMMIT();
    load_stage(1, 1); CP_COMMIT();
    cp_wait<1>();
    __syncthreads();
    mma_m128n64<AS1, 4>(sb, 0, PA1, acc, wid, lid);
    cp_wait<0>();
    __syncthreads();
    mma_m128n64<AS1, 4>(sb, STG1, STG1 + PA1, acc, wid, lid);
    __syncthreads();

    // epilogue: bias + relu -> fp16 staged (128 rows x 64 cols, stride 72 halves)
    int arow = (wid >> 1) * 32, brow = (wid & 1) * 32;
    __half2* sh2 = (__half2*)smem;          // 36 half2 per row
    #pragma unroll
    for (int mi = 0; mi < 2; mi++)
        #pragma unroll
        for (int n = 0; n < 4; n++) {
            int r = arow + mi * 16 + (lid >> 2);
            int c = brow + n * 8 + (lid & 3) * 2;
            float v0 = fmaxf(acc[mi][n][0] + bias[c], 0.f);
            float v1 = fmaxf(acc[mi][n][1] + bias[c + 1], 0.f);
            float v2 = fmaxf(acc[mi][n][2] + bias[c], 0.f);
            float v3 = fmaxf(acc[mi][n][3] + bias[c + 1], 0.f);
            sh2[r * 36 + (c >> 1)]       = __halves2half2(__float2half_rn(v0), __float2half_rn(v1));
            sh2[(r + 8) * 36 + (c >> 1)] = __halves2half2(__float2half_rn(v2), __float2half_rn(v3));
        }
    __syncthreads();
    uint4* HF = (uint4*)g_hf;
    #pragma unroll
    for (int i = 0; i < 4; i++) {           // 128 rows x 8 uint4
        int idx = tid + i * 256;
        int r = idx >> 3, c = idx & 7;
        uint32_t so = (uint32_t)((r * AS1 + c * 8) * 2);
        HF[(size_t)(m0 + r) * 256 + (n0 >> 3) + c] = *(uint4*)(smem + so);
    }
}

// ---------------- K4: GEMM2: M64, K-split 2, 4-stage pipeline ------------------
#define AS2 40
#define ST_A (64 * AS2 * 2)            // 5120
#define ST_B (128 * AS2 * 2)           // 10240
#define BUF2 (ST_A + ST_B)             // 15360 per stage
#define G2_SMEM (4 * BUF2 + 512)       // 61952

__global__ __launch_bounds__(256, 3)
void gemm2_mma() {
    extern __shared__ char smem[];
    uint32_t sb = smem_u32(smem);
    int tid = threadIdx.x, wid = tid >> 5, lid = tid & 31;
    int m0 = blockIdx.x * 64;
    int ksp = blockIdx.y;

    const uint4* srcA = (const uint4*)g_hf  + (size_t)m0 * 256 + ksp * 128;
    const uint4* srcB = (const uint4*)g_w2f + ksp * 128;
    float* dst = ksp ? g_ff1 : g_ff0;

    auto load_chunk = [&](int c, int buf) {
        uint32_t bb = sb + buf * BUF2;
        {
            int r = tid >> 2, cc = tid & 3;
            uint32_t so = (uint32_t)((r * AS2 + cc * 8) * 2);
            cp16(bb + so, srcA + (size_t)r * 256 + c * 4 + cc);
        }
        #pragma unroll
        for (int i = 0; i < 2; i++) {
            int idx = tid + i * 256;
            int r = idx >> 2, cc = idx & 3;
            uint32_t so = (uint32_t)((r * AS2 + cc * 8) * 2);
            cp16(bb + ST_A + so, srcB + (size_t)r * 256 + c * 4 + cc);
        }
    };

    float acc[2][4][4] = {};
    load_chunk(0, 0); CP_COMMIT();
    load_chunk(1, 1); CP_COMMIT();
    load_chunk(2, 2); CP_COMMIT();

    for (int c = 0; c < 32; c++) {
        cp_wait<2>();
        __syncthreads();
        uint32_t bb = sb + (c & 3) * BUF2;
        mma_tile64<AS2, 2>(bb, 0, ST_A, acc, wid, lid);
        __syncthreads();
        if (c + 3 < 32) {
            load_chunk(c + 3, (c + 3) & 3);
            CP_COMMIT();
        } else {
            CP_COMMIT();
        }
    }

    int wm = wid >> 2, wn = wid & 3;
    int arow = wm * 32, brow = wn * 32;
    #pragma unroll
    for (int mi = 0; mi < 2; mi++)
        #pragma unroll
        for (int n = 0; n < 4; n++) {
            int gr = m0 + arow + mi * 16 + (lid >> 2);
            int cc = brow + n * 8 + (lid & 3) * 2;
            if (cc < DIM) {
                dst[(size_t)gr * DIM + cc]       = acc[mi][n][0];
                dst[(size_t)(gr + 8) * DIM + cc] = acc[mi][n][2];
            }
            if (cc + 1 < DIM) {
                dst[(size_t)gr * DIM + cc + 1]       = acc[mi][n][1];
                dst[(size_t)(gr + 8) * DIM + cc + 1] = acc[mi][n][3];
            }
        }
}

// ---------------- K5: fused LN2 + scoring (M-tile 64, 256 CTAs) ----------------
__global__ __launch_bounds__(256, 3)
void ln2_score_tc(const float* __restrict__ ln2_g, const float* __restrict__ ln2_b,
                  const int* __restrict__ items, const float* __restrict__ rec_b,
                  const float* __restrict__ b2, float* __restrict__ out) {
    extern __shared__ char smem[];
    uint32_t sb = smem_u32(smem);
    int tid = threadIdx.x, wid = tid >> 5, lid = tid & 31;
    int m0 = blockIdx.x * 64;
    float* srecb = (float*)(smem + F2_T);
    float* sb2   = (float*)(smem + F2_T + 512);
    if (tid < KPAD) {
        srecb[tid] = (tid < DIM) ? rec_b[tid] : 0.f;
        sb2[tid]   = (tid < DIM) ? b2[tid]    : 0.f;
    }

    const uint4* B4 = (const uint4*)g_recf;
    #pragma unroll
    for (int i = 0; i < 8; i++) {
        int idx = tid + i * 256;
        int r = idx >> 4, c = idx & 15;
        uint32_t so = (uint32_t)((r * FAS + c * 8) * 2);
        *(uint4*)(smem + F2_B + so) = B4[r * 16 + c];
    }
    __syncthreads();

    for (int rr = 0; rr < 8; rr++) {
        int r = wid * 8 + rr;
        float v[4], s = 0.f, sq = 0.f;
        #pragma unroll
        for (int q = 0; q < 4; q++) {
            int t = lid + q * 32;
            v[q] = 0.f;
            if (t < DIM) {
                size_t o = (size_t)(m0 + r) * DIM + t;
                v[q] = g_x1[(size_t)(m0 + r) * KPAD + t]
                     + (g_ff0[o] + g_ff1[o] + sb2[t]);
            }
            s += v[q]; sq += v[q] * v[q];
        }
        #pragma unroll
        for (int off = 16; off; off >>= 1) {
            s  += __shfl_xor_sync(0xffffffffu, s,  off);
            sq += __shfl_xor_sync(0xffffffffu, sq, off);
        }
        float m = s / DIM;
        float inv = rsqrtf(sq / DIM - m * m + EPS);
        #pragma unroll
        for (int q = 0; q < 4; q++) {
            int t = lid + q * 32;
            float o = (t < DIM) ? (v[q] - m) * inv * ln2_g[t] + ln2_b[t] : 0.f;
            *(fp16*)(smem + F2_A + ((r * FAS + t) << 1)) = __float2half_rn(o);
        }
    }
    __syncthreads();

    float acc[2][4][4] = {};
    mma_tile64<FAS, 8>(sb, F2_A, F2_B, acc, wid, lid);
    __syncthreads();

    float* fbuf = (float*)smem;
    int wm = wid >> 2, wn = wid & 3;
    int arow = wm * 32, brow = wn * 32;
    #pragma unroll
    for (int mi = 0; mi < 2; mi++)
        #pragma unroll
        for (int n = 0; n < 4; n++) {
            int r = arow + mi * 16 + (lid >> 2);
            int c = brow + n * 8 + (lid & 3) * 2;
            fbuf[r * 128 + c]           = acc[mi][n][0];
            fbuf[r * 128 + c + 1]       = acc[mi][n][1];
            fbuf[(r + 8) * 128 + c]     = acc[mi][n][2];
            fbuf[(r + 8) * 128 + c + 1] = acc[mi][n][3];
        }
    __syncthreads();

    for (int o = tid; o < 64 * KPRED; o += 256) {
        int r = o / KPRED, k = o - r * KPRED;
        int idx = items[(size_t)(m0 + r) * KPRED + k];
        out[(size_t)(m0 + r) * KPRED + k] = fbuf[r * 128 + idx] + srecb[idx];
    }
}

// ---------------- launch ------------------------------------------------------
extern "C" void kernel_launch(void* const* d_in, const int* in_sizes, int n_in,
                              void* d_out, int out_size) {
    const int*   item_seq   = (const int*)  d_in[0];
    const int*   items_pred = (const int*)  d_in[1];
    const float* item_emb_w = (const float*)d_in[2];
    const float* rec_emb_w  = (const float*)d_in[3];
    const float* rec_b_w    = (const float*)d_in[4];
    const float* in_proj_w  = (const float*)d_in[5];
    const float* in_proj_b  = (const float*)d_in[6];
    const float* out_proj_w = (const float*)d_in[7];
    const float* out_proj_b = (const float*)d_in[8];
    const float* ln1_g      = (const float*)d_in[9];
    const float* ln1_b      = (const float*)d_in[10];
    const float* ln2_g      = (const float*)d_in[11];
    const float* ln2_b      = (const float*)d_in[12];
    const float* ffn_w1     = (const float*)d_in[13];
    const float* ffn_b1     = (const float*)d_in[14];
    const float* ffn_w2     = (const float*)d_in[15];
    const float* ffn_b2     = (const float*)d_in[16];
    float* out = (float*)d_out;

    int B = in_sizes[0] / SEQ_L;

    cudaFuncSetAttribute(attn_ln1_tc,  cudaFuncAttributeMaxDynamicSharedMemorySize, F2_SMEM);
    cudaFuncSetAttribute(ln2_score_tc, cudaFuncAttributeMaxDynamicSharedMemorySize, F2_SMEM);
    cudaFuncSetAttribute(gemm1_mma, cudaFuncAttributeMaxDynamicSharedMemorySize, G1_SMEM);
    cudaFuncSetAttribute(gemm2_mma, cudaFuncAttributeMaxDynamicSharedMemorySize, G2_SMEM);

    embed_prep<<<B / 2 + 2176, 256>>>(item_seq, item_emb_w,
                                      in_proj_w, in_proj_b, out_proj_w, out_proj_b,
                                      rec_emb_w, ffn_w1, ffn_w2);
    attn_ln1_tc<<<B / 64, 256, F2_SMEM>>>(ln1_g, ln1_b);
    gemm1_mma<<<dim3(B / 128, FFDIM / 64), 256, G1_SMEM>>>(ffn_b1);
    gemm2_mma<<<dim3(B / 64, 2), 256, G2_SMEM>>>();
    ln2_score_tc<<<B / 64, 256, F2_SMEM>>>(ln2_g, ln2_b, items_pred, rec_b_w,
                                           ffn_b2, out);
}

// round 15
// speedup vs baseline: 2.4940x; 1.0093x over previous
#include <cuda_runtime.h>
#include <cuda_fp16.h>
#include <cstdint>

#define SEQ_L 50
#define DIM 100
#define KPAD 128
#define FFDIM 2048
#define KPRED 100
#define EPS 1e-5f
#define BMAX 16384

typedef __half fp16;

// ---------------- scratch (device globals) ---------------------------------
__device__ float g_x  [BMAX * DIM];
__device__ float g_x1 [BMAX * KPAD];
__device__ float g_ff0[BMAX * DIM];
__device__ float g_ff1[BMAX * DIM];
__device__ float g_c  [KPAD];
__device__ fp16  g_Mf  [KPAD * KPAD];
__device__ fp16  g_recf[KPAD * KPAD];
__device__ fp16  g_x1f[BMAX * KPAD];
__device__ fp16  g_w1f[FFDIM * KPAD];
__device__ fp16  g_hf [(size_t)BMAX * FFDIM];
__device__ fp16  g_w2f[KPAD * FFDIM];

// ---------------- helpers ----------------------------------------------------
__device__ __forceinline__ uint32_t smem_u32(const void* p) {
    uint32_t a;
    asm("{ .reg .u64 t; cvta.to.shared.u64 t, %1; cvt.u32.u64 %0, t; }" : "=r"(a) : "l"(p));
    return a;
}
__device__ __forceinline__ void ldsm_x4(uint32_t addr, uint32_t& r0, uint32_t& r1,
                                        uint32_t& r2, uint32_t& r3) {
    asm volatile("ldmatrix.sync.aligned.m8n8.x4.shared.b16 {%0,%1,%2,%3}, [%4];"
                 : "=r"(r0), "=r"(r1), "=r"(r2), "=r"(r3) : "r"(addr));
}
__device__ __forceinline__ void mma_f16(float* d, const uint32_t* a, const uint32_t* b) {
    asm volatile("mma.sync.aligned.m16n8k16.row.col.f32.f16.f16.f32 "
                 "{%0,%1,%2,%3}, {%4,%5,%6,%7}, {%8,%9}, {%0,%1,%2,%3};"
                 : "+f"(d[0]), "+f"(d[1]), "+f"(d[2]), "+f"(d[3])
                 : "r"(a[0]), "r"(a[1]), "r"(a[2]), "r"(a[3]), "r"(b[0]), "r"(b[1]));
}
__device__ __forceinline__ void cp16(uint32_t saddr, const void* g) {
    asm volatile("cp.async.cg.shared.global [%0], [%1], 16;" :: "r"(saddr), "l"(g));
}
#define CP_COMMIT() asm volatile("cp.async.commit_group;" ::: "memory")
template<int N> __device__ __forceinline__ void cp_wait() {
    asm volatile("cp.async.wait_group %0;" :: "n"(N) : "memory");
}

// M128 x N64 warp-tiled MMA phase (8 warps as 4m x 2n, warp tile 32x32) — gemm1
template<int AS, int NKS>
__device__ __forceinline__ void mma_m128n64(uint32_t sb, uint32_t oA, uint32_t oB,
                                            float acc[2][4][4], int wid, int lid) {
    int arow = (wid >> 1) * 32, brow = (wid & 1) * 32;
    int lr = lid & 15, lc8 = (lid >> 4) << 3;
    #pragma unroll
    for (int ks = 0; ks < NKS; ks++) {
        int k0 = ks * 16;
        uint32_t a[2][4];
        #pragma unroll
        for (int mi = 0; mi < 2; mi++) {
            uint32_t off = (uint32_t)(((arow + mi * 16 + lr) * AS + k0 + lc8) * 2);
            ldsm_x4(sb + oA + off, a[mi][0], a[mi][1], a[mi][2], a[mi][3]);
        }
        uint32_t b[4][2];
        #pragma unroll
        for (int nj = 0; nj < 2; nj++) {
            uint32_t off = (uint32_t)(((brow + nj * 16 + lr) * AS + k0 + lc8) * 2);
            uint32_t r0, r1, r2, r3;
            ldsm_x4(sb + oB + off, r0, r1, r2, r3);
            b[nj * 2][0] = r0; b[nj * 2 + 1][0] = r1;
            b[nj * 2][1] = r2; b[nj * 2 + 1][1] = r3;
        }
        #pragma unroll
        for (int mi = 0; mi < 2; mi++)
            #pragma unroll
            for (int n = 0; n < 4; n++)
                mma_f16(acc[mi][n], a[mi], b[n]);
    }
}

// M64 x N128 warp-tiled MMA phase (8 warps as 2m x 4n, warp tile 32x32)
template<int AS, int NKS>
__device__ __forceinline__ void mma_tile64(uint32_t sb, uint32_t oA, uint32_t oB,
                                           float acc[2][4][4], int wid, int lid) {
    int wm = wid >> 2, wn = wid & 3;
    int arow = wm * 32, brow = wn * 32;
    int lr = lid & 15, lc8 = (lid >> 4) << 3;
    #pragma unroll
    for (int ks = 0; ks < NKS; ks++) {
        int k0 = ks * 16;
        uint32_t a[2][4];
        #pragma unroll
        for (int mi = 0; mi < 2; mi++) {
            uint32_t off = (uint32_t)(((arow + mi * 16 + lr) * AS + k0 + lc8) * 2);
            ldsm_x4(sb + oA + off, a[mi][0], a[mi][1], a[mi][2], a[mi][3]);
        }
        uint32_t b[4][2];
        #pragma unroll
        for (int nj = 0; nj < 2; nj++) {
            uint32_t off = (uint32_t)(((brow + nj * 16 + lr) * AS + k0 + lc8) * 2);
            uint32_t r0, r1, r2, r3;
            ldsm_x4(sb + oB + off, r0, r1, r2, r3);
            b[nj * 2][0] = r0; b[nj * 2 + 1][0] = r1;
            b[nj * 2][1] = r2; b[nj * 2 + 1][1] = r3;
        }
        #pragma unroll
        for (int mi = 0; mi < 2; mi++)
            #pragma unroll
            for (int n = 0; n < 4; n++)
                mma_f16(acc[mi][n], a[mi], b[n]);
    }
}

// ---------------- K0: merged embed gather + prep -------------------------------
__global__ void embed_prep(const int* __restrict__ seq,
                           const float* __restrict__ emb,
                           const float* __restrict__ in_proj_w,
                           const float* __restrict__ in_proj_b,
                           const float* __restrict__ out_proj_w,
                           const float* __restrict__ out_proj_b,
                           const float* __restrict__ rec_emb,
                           const float* __restrict__ w1,
                           const float* __restrict__ w2) {
    int bid = blockIdx.x, tid = threadIdx.x;
    if (bid < 8192) {
        __shared__ int s_idx[2 * SEQ_L];
        int half = tid >> 7;
        int t = tid & 127;
        int b = bid * 2 + half;
        if (t < SEQ_L) s_idx[half * SEQ_L + t] = seq[b * SEQ_L + t];
        __syncthreads();
        if (t < DIM) {
            float acc = 0.f;
            #pragma unroll 5
            for (int l = 0; l < SEQ_L; l++)
                acc += emb[(size_t)s_idx[half * SEQ_L + l] * DIM + t];
            g_x[b * DIM + t] = acc;
        }
        return;
    }
    int pid = bid - 8192;
    if (pid < 64) {
        int i = pid * 2 + (tid >> 7);
        int j = tid & 127;
        const float* Wv = in_proj_w + 2 * DIM * DIM;
        const float* bv = in_proj_b + 2 * DIM;
        float mv = 0.f;
        if (i < DIM && j < DIM) {
            #pragma unroll 4
            for (int k = 0; k < DIM; k++)
                mv += out_proj_w[i * DIM + k] * Wv[k * DIM + j];
        }
        g_Mf[i * KPAD + j] = __float2half_rn(mv);
        if (j == 0) {
            float s = 0.f;
            if (i < DIM) {
                s = out_proj_b[i];
                for (int k = 0; k < DIM; k++)
                    s += out_proj_w[i * DIM + k] * bv[k];
            }
            g_c[i] = s;
        }
    } else if (pid < 128) {
        int idx = (pid - 64) * 256 + tid;
        int n = idx >> 7, k = idx & 127;
        float v = (n < DIM && k < DIM) ? rec_emb[n * DIM + k] : 0.f;
        g_recf[idx] = __float2half_rn(v);
    } else if (pid < 128 + 1024) {
        int idx = (pid - 128) * 256 + tid;
        int n = idx >> 7, k = idx & 127;
        float v = (k < DIM) ? w1[n * DIM + k] : 0.f;
        g_w1f[idx] = __float2half_rn(v);
    } else {
        int idx = (pid - 1152) * 256 + tid;
        int n = idx >> 11, k = idx & 2047;
        float v = (n < DIM) ? w2[n * FFDIM + k] : 0.f;
        g_w2f[idx] = __float2half_rn(v);
    }
}

// ---------------- M64 fused-tile smem layout (attn_ln1 / ln2_score) -----------
#define FAS 136
#define A64_SZ (64 * FAS * 2)
#define B128_SZ (128 * FAS * 2)
#define F2_A 0
#define F2_B A64_SZ
#define F2_T (A64_SZ + B128_SZ)
#define F2_SMEM (F2_T + 1024)

// ---------------- K2: fused attn + LN1 (M-tile 64, 256 CTAs) ------------------
__global__ __launch_bounds__(256, 3)
void attn_ln1_tc(const float* __restrict__ ln1_g, const float* __restrict__ ln1_b) {
    extern __shared__ char smem[];
    uint32_t sb = smem_u32(smem);
    int tid = threadIdx.x, wid = tid >> 5, lid = tid & 31;
    int m0 = blockIdx.x * 64;
    float* cvec = (float*)(smem + F2_T);
    if (tid < KPAD) cvec[tid] = g_c[tid];

    for (int idx = tid; idx < 64 * 128; idx += 256) {
        int r = idx >> 7, j = idx & 127;
        float v = (j < DIM) ? g_x[(size_t)(m0 + r) * DIM + j] : 0.f;
        *(fp16*)(smem + F2_A + ((r * FAS + j) << 1)) = __float2half_rn(v);
    }
    const uint4* B4 = (const uint4*)g_Mf;
    #pragma unroll
    for (int i = 0; i < 8; i++) {
        int idx = tid + i * 256;
        int r = idx >> 4, c = idx & 15;
        uint32_t so = (uint32_t)((r * FAS + c * 8) * 2);
        *(uint4*)(smem + F2_B + so) = B4[r * 16 + c];
    }
    __syncthreads();

    float acc[2][4][4] = {};
    mma_tile64<FAS, 8>(sb, F2_A, F2_B, acc, wid, lid);
    __syncthreads();

    float* ybuf = (float*)smem;
    int wm = wid >> 2, wn = wid & 3;
    int arow = wm * 32, brow = wn * 32;
    #pragma unroll
    for (int mi = 0; mi < 2; mi++)
        #pragma unroll
        for (int n = 0; n < 4; n++) {
            int r = arow + mi * 16 + (lid >> 2);
            int c = brow + n * 8 + (lid & 3) * 2;
            float x0 = (c     < DIM) ? g_x[(size_t)(m0 + r) * DIM + c]     : 0.f;
            float x1v= (c + 1 < DIM) ? g_x[(size_t)(m0 + r) * DIM + c + 1] : 0.f;
            float x2 = (c     < DIM) ? g_x[(size_t)(m0 + r + 8) * DIM + c]     : 0.f;
            float x3 = (c + 1 < DIM) ? g_x[(size_t)(m0 + r + 8) * DIM + c + 1] : 0.f;
            ybuf[r * 132 + c]           = acc[mi][n][0] + x0  + cvec[c];
            ybuf[r * 132 + c + 1]       = acc[mi][n][1] + x1v + cvec[c + 1];
            ybuf[(r + 8) * 132 + c]     = acc[mi][n][2] + x2  + cvec[c];
            ybuf[(r + 8) * 132 + c + 1] = acc[mi][n][3] + x3  + cvec[c + 1];
        }
    __syncthreads();

    for (int rr = 0; rr < 8; rr++) {
        int r = wid * 8 + rr;
        float v[4], s = 0.f, sq = 0.f;
        #pragma unroll
        for (int q = 0; q < 4; q++) {
            int t = lid + q * 32;
            v[q] = (t < DIM) ? ybuf[r * 132 + t] : 0.f;
            s += v[q]; sq += v[q] * v[q];
        }
        #pragma unroll
        for (int off = 16; off; off >>= 1) {
            s  += __shfl_xor_sync(0xffffffffu, s,  off);
            sq += __shfl_xor_sync(0xffffffffu, sq, off);
        }
        float m = s / DIM;
        float inv = rsqrtf(sq / DIM - m * m + EPS);
        #pragma unroll
        for (int q = 0; q < 4; q++) {
            int t = lid + q * 32;
            float o = (t < DIM) ? (v[q] - m) * inv * ln1_g[t] + ln1_b[t] : 0.f;
            g_x1 [(size_t)(m0 + r) * KPAD + t] = o;
            g_x1f[(size_t)(m0 + r) * KPAD + t] = __float2half_rn(o);
        }
    }
}

// ---------------- K3: GEMM1: tile 128x64, occ 3, cp.async 2-stage --------------
#define AS1 72
#define PA1 (128 * AS1 * 2)
#define PB1 (64 * AS1 * 2)
#define STG1 (PA1 + PB1)
#define S1_BIAS (2 * STG1)
#define G1_SMEM (2 * STG1 + 512)

__global__ __launch_bounds__(256, 3)
void gemm1_mma(const float* __restrict__ b1) {
    extern __shared__ char smem[];
    uint32_t sb = smem_u32(smem);
    int tid = threadIdx.x, wid = tid >> 5, lid = tid & 31;
    int m0 = blockIdx.x * 128, n0 = blockIdx.y * 64;
    float* bias = (float*)(smem + S1_BIAS);
    if (tid < 64) bias[tid] = b1[n0 + tid];

    const uint4* A4 = (const uint4*)g_x1f + (size_t)m0 * 16;
    const uint4* B4 = (const uint4*)g_w1f + (size_t)n0 * 16;

    auto load_stage = [&](int kh, int buf) {
        uint32_t bb = sb + buf * STG1;
        #pragma unroll
        for (int i = 0; i < 4; i++) {
            int idx = tid + i * 256;
            int r = idx >> 3, c = idx & 7;
            uint32_t so = (uint32_t)((r * AS1 + c * 8) * 2);
            cp16(bb + so, A4 + (size_t)r * 16 + kh * 8 + c);
        }
        #pragma unroll
        for (int i = 0; i < 2; i++) {
            int idx = tid + i * 256;
            int r = idx >> 3, c = idx & 7;
            uint32_t so = (uint32_t)((r * AS1 + c * 8) * 2);
            cp16(bb + PA1 + so, B4 + (size_t)r * 16 + kh * 8 + c);
        }
    };

    float acc[2][4][4] = {};
    load_stage(0, 0); CP_COMMIT();
    load_stage(1, 1); CP_COMMIT();
    cp_wait<1>();
    __syncthreads();
    mma_m128n64<AS1, 4>(sb, 0, PA1, acc, wid, lid);
    cp_wait<0>();
    __syncthreads();
    mma_m128n64<AS1, 4>(sb, STG1, STG1 + PA1, acc, wid, lid);
    __syncthreads();

    int arow = (wid >> 1) * 32, brow = (wid & 1) * 32;
    __half2* sh2 = (__half2*)smem;
    #pragma unroll
    for (int mi = 0; mi < 2; mi++)
        #pragma unroll
        for (int n = 0; n < 4; n++) {
            int r = arow + mi * 16 + (lid >> 2);
            int c = brow + n * 8 + (lid & 3) * 2;
            float v0 = fmaxf(acc[mi][n][0] + bias[c], 0.f);
            float v1 = fmaxf(acc[mi][n][1] + bias[c + 1], 0.f);
            float v2 = fmaxf(acc[mi][n][2] + bias[c], 0.f);
            float v3 = fmaxf(acc[mi][n][3] + bias[c + 1], 0.f);
            sh2[r * 36 + (c >> 1)]       = __halves2half2(__float2half_rn(v0), __float2half_rn(v1));
            sh2[(r + 8) * 36 + (c >> 1)] = __halves2half2(__float2half_rn(v2), __float2half_rn(v3));
        }
    __syncthreads();
    uint4* HF = (uint4*)g_hf;
    #pragma unroll
    for (int i = 0; i < 4; i++) {
        int idx = tid + i * 256;
        int r = idx >> 3, c = idx & 7;
        uint32_t so = (uint32_t)((r * AS1 + c * 8) * 2);
        HF[(size_t)(m0 + r) * 256 + (n0 >> 3) + c] = *(uint4*)(smem + so);
    }
}

// ---------------- K4: GEMM2: M64, K-split 2, 4-stage, single-sync loop ---------
#define AS2 40
#define ST_A (64 * AS2 * 2)
#define ST_B (128 * AS2 * 2)
#define BUF2 (ST_A + ST_B)
#define G2_SMEM (4 * BUF2 + 512)

__global__ __launch_bounds__(256, 3)
void gemm2_mma() {
    extern __shared__ char smem[];
    uint32_t sb = smem_u32(smem);
    int tid = threadIdx.x, wid = tid >> 5, lid = tid & 31;
    int m0 = blockIdx.x * 64;
    int ksp = blockIdx.y;

    const uint4* srcA = (const uint4*)g_hf  + (size_t)m0 * 256 + ksp * 128;
    const uint4* srcB = (const uint4*)g_w2f + ksp * 128;
    float* dst = ksp ? g_ff1 : g_ff0;

    auto load_chunk = [&](int c, int buf) {
        uint32_t bb = sb + buf * BUF2;
        {
            int r = tid >> 2, cc = tid & 3;
            uint32_t so = (uint32_t)((r * AS2 + cc * 8) * 2);
            cp16(bb + so, srcA + (size_t)r * 256 + c * 4 + cc);
        }
        #pragma unroll
        for (int i = 0; i < 2; i++) {
            int idx = tid + i * 256;
            int r = idx >> 2, cc = idx & 3;
            uint32_t so = (uint32_t)((r * AS2 + cc * 8) * 2);
            cp16(bb + ST_A + so, srcB + (size_t)r * 256 + c * 4 + cc);
        }
    };

    float acc[2][4][4] = {};
    load_chunk(0, 0); CP_COMMIT();
    load_chunk(1, 1); CP_COMMIT();
    load_chunk(2, 2); CP_COMMIT();

    // single-sync pipeline: barrier proves mma(c-1) done everywhere, so buffer
    // (c+3)%4 == (c-1)%4 is free to overwrite before mma(c) issues.
    for (int c = 0; c < 32; c++) {
        cp_wait<2>();
        __syncthreads();
        if (c + 3 < 32) load_chunk(c + 3, (c + 3) & 3);
        CP_COMMIT();                       // dummy commits keep wait<2> arithmetic
        uint32_t bb = sb + (c & 3) * BUF2;
        mma_tile64<AS2, 2>(bb, 0, ST_A, acc, wid, lid);
    }

    int wm = wid >> 2, wn = wid & 3;
    int arow = wm * 32, brow = wn * 32;
    #pragma unroll
    for (int mi = 0; mi < 2; mi++)
        #pragma unroll
        for (int n = 0; n < 4; n++) {
            int gr = m0 + arow + mi * 16 + (lid >> 2);
            int cc = brow + n * 8 + (lid & 3) * 2;
            if (cc < DIM) {
                dst[(size_t)gr * DIM + cc]       = acc[mi][n][0];
                dst[(size_t)(gr + 8) * DIM + cc] = acc[mi][n][2];
            }
            if (cc + 1 < DIM) {
                dst[(size_t)gr * DIM + cc + 1]       = acc[mi][n][1];
                dst[(size_t)(gr + 8) * DIM + cc + 1] = acc[mi][n][3];
            }
        }
}

// ---------------- K5: fused LN2 + scoring (M-tile 64, 256 CTAs) ----------------
__global__ __launch_bounds__(256, 3)
void ln2_score_tc(const float* __restrict__ ln2_g, const float* __restrict__ ln2_b,
                  const int* __restrict__ items, const float* __restrict__ rec_b,
                  const float* __restrict__ b2, float* __restrict__ out) {
    extern __shared__ char smem[];
    uint32_t sb = smem_u32(smem);
    int tid = threadIdx.x, wid = tid >> 5, lid = tid & 31;
    int m0 = blockIdx.x * 64;
    float* srecb = (float*)(smem + F2_T);
    float* sb2   = (float*)(smem + F2_T + 512);
    if (tid < KPAD) {
        srecb[tid] = (tid < DIM) ? rec_b[tid] : 0.f;
        sb2[tid]   = (tid < DIM) ? b2[tid]    : 0.f;
    }

    const uint4* B4 = (const uint4*)g_recf;
    #pragma unroll
    for (int i = 0; i < 8; i++) {
        int idx = tid + i * 256;
        int r = idx >> 4, c = idx & 15;
        uint32_t so = (uint32_t)((r * FAS + c * 8) * 2);
        *(uint4*)(smem + F2_B + so) = B4[r * 16 + c];
    }
    __syncthreads();

    for (int rr = 0; rr < 8; rr++) {
        int r = wid * 8 + rr;
        float v[4], s = 0.f, sq = 0.f;
        #pragma unroll
        for (int q = 0; q < 4; q++) {
            int t = lid + q * 32;
            v[q] = 0.f;
            if (t < DIM) {
                size_t o = (size_t)(m0 + r) * DIM + t;
                v[q] = g_x1[(size_t)(m0 + r) * KPAD + t]
                     + (g_ff0[o] + g_ff1[o] + sb2[t]);
            }
            s += v[q]; sq += v[q] * v[q];
        }
        #pragma unroll
        for (int off = 16; off; off >>= 1) {
            s  += __shfl_xor_sync(0xffffffffu, s,  off);
            sq += __shfl_xor_sync(0xffffffffu, sq, off);
        }
        float m = s / DIM;
        float inv = rsqrtf(sq / DIM - m * m + EPS);
        #pragma unroll
        for (int q = 0; q < 4; q++) {
            int t = lid + q * 32;
            float o = (t < DIM) ? (v[q] - m) * inv * ln2_g[t] + ln2_b[t] : 0.f;
            *(fp16*)(smem + F2_A + ((r * FAS + t) << 1)) = __float2half_rn(o);
        }
    }
    __syncthreads();

    float acc[2][4][4] = {};
    mma_tile64<FAS, 8>(sb, F2_A, F2_B, acc, wid, lid);
    __syncthreads();

    float* fbuf = (float*)smem;
    int wm = wid >> 2, wn = wid & 3;
    int arow = wm * 32, brow = wn * 32;
    #pragma unroll
    for (int mi = 0; mi < 2; mi++)
        #pragma unroll
        for (int n = 0; n < 4; n++) {
            int r = arow + mi * 16 + (lid >> 2);
            int c = brow + n * 8 + (lid & 3) * 2;
            fbuf[r * 128 + c]           = acc[mi][n][0];
            fbuf[r * 128 + c + 1]       = acc[mi][n][1];
            fbuf[(r + 8) * 128 + c]     = acc[mi][n][2];
            fbuf[(r + 8) * 128 + c + 1] = acc[mi][n][3];
        }
    __syncthreads();

    for (int o = tid; o < 64 * KPRED; o += 256) {
        int r = o / KPRED, k = o - r * KPRED;
        int idx = items[(size_t)(m0 + r) * KPRED + k];
        out[(size_t)(m0 + r) * KPRED + k] = fbuf[r * 128 + idx] + srecb[idx];
    }
}

// ---------------- launch ------------------------------------------------------
extern "C" void kernel_launch(void* const* d_in, const int* in_sizes, int n_in,
                              void* d_out, int out_size) {
    const int*   item_seq   = (const int*)  d_in[0];
    const int*   items_pred = (const int*)  d_in[1];
    const float* item_emb_w = (const float*)d_in[2];
    const float* rec_emb_w  = (const float*)d_in[3];
    const float* rec_b_w    = (const float*)d_in[4];
    const float* in_proj_w  = (const float*)d_in[5];
    const float* in_proj_b  = (const float*)d_in[6];
    const float* out_proj_w = (const float*)d_in[7];
    const float* out_proj_b = (const float*)d_in[8];
    const float* ln1_g      = (const float*)d_in[9];
    const float* ln1_b      = (const float*)d_in[10];
    const float* ln2_g      = (const float*)d_in[11];
    const float* ln2_b      = (const float*)d_in[12];
    const float* ffn_w1     = (const float*)d_in[13];
    const float* ffn_b1     = (const float*)d_in[14];
    const float* ffn_w2     = (const float*)d_in[15];
    const float* ffn_b2     = (const float*)d_in[16];
    float* out = (float*)d_out;

    int B = in_sizes[0] / SEQ_L;

    cudaFuncSetAttribute(attn_ln1_tc,  cudaFuncAttributeMaxDynamicSharedMemorySize, F2_SMEM);
    cudaFuncSetAttribute(ln2_score_tc, cudaFuncAttributeMaxDynamicSharedMemorySize, F2_SMEM);
    cudaFuncSetAttribute(gemm1_mma, cudaFuncAttributeMaxDynamicSharedMemorySize, G1_SMEM);
    cudaFuncSetAttribute(gemm2_mma, cudaFuncAttributeMaxDynamicSharedMemorySize, G2_SMEM);

    embed_prep<<<B / 2 + 2176, 256>>>(item_seq, item_emb_w,
                                      in_proj_w, in_proj_b, out_proj_w, out_proj_b,
                                      rec_emb_w, ffn_w1, ffn_w2);
    attn_ln1_tc<<<B / 64, 256, F2_SMEM>>>(ln1_g, ln1_b);
    gemm1_mma<<<dim3(B / 128, FFDIM / 64), 256, G1_SMEM>>>(ffn_b1);
    gemm2_mma<<<dim3(B / 64, 2), 256, G2_SMEM>>>();
    ln2_score_tc<<<B / 64, 256, F2_SMEM>>>(ln2_g, ln2_b, items_pred, rec_b_w,
                                           ffn_b2, out);
}

// round 16
// speedup vs baseline: 2.5580x; 1.0256x over previous
#include <cuda_runtime.h>
#include <cuda_fp16.h>
#include <cstdint>

#define SEQ_L 50
#define DIM 100
#define KPAD 128
#define FFDIM 2048
#define KPRED 100
#define EPS 1e-5f
#define BMAX 16384

typedef __half fp16;

// ---------------- scratch (device globals) ---------------------------------
__device__ float g_x  [BMAX * DIM];
__device__ float g_x1 [BMAX * KPAD];
__device__ float g_ff0[BMAX * DIM];
__device__ float g_ff1[BMAX * DIM];
__device__ float g_ff2[BMAX * DIM];
__device__ float g_ff3[BMAX * DIM];
__device__ float g_c  [KPAD];
__device__ fp16  g_Mf  [KPAD * KPAD];
__device__ fp16  g_recf[KPAD * KPAD];
__device__ fp16  g_x1f[BMAX * KPAD];
__device__ fp16  g_w1f[FFDIM * KPAD];
__device__ fp16  g_hf [(size_t)BMAX * FFDIM];
__device__ fp16  g_w2f[KPAD * FFDIM];

// ---------------- helpers ----------------------------------------------------
__device__ __forceinline__ uint32_t smem_u32(const void* p) {
    uint32_t a;
    asm("{ .reg .u64 t; cvta.to.shared.u64 t, %1; cvt.u32.u64 %0, t; }" : "=r"(a) : "l"(p));
    return a;
}
__device__ __forceinline__ void ldsm_x4(uint32_t addr, uint32_t& r0, uint32_t& r1,
                                        uint32_t& r2, uint32_t& r3) {
    asm volatile("ldmatrix.sync.aligned.m8n8.x4.shared.b16 {%0,%1,%2,%3}, [%4];"
                 : "=r"(r0), "=r"(r1), "=r"(r2), "=r"(r3) : "r"(addr));
}
__device__ __forceinline__ void mma_f16(float* d, const uint32_t* a, const uint32_t* b) {
    asm volatile("mma.sync.aligned.m16n8k16.row.col.f32.f16.f16.f32 "
                 "{%0,%1,%2,%3}, {%4,%5,%6,%7}, {%8,%9}, {%0,%1,%2,%3};"
                 : "+f"(d[0]), "+f"(d[1]), "+f"(d[2]), "+f"(d[3])
                 : "r"(a[0]), "r"(a[1]), "r"(a[2]), "r"(a[3]), "r"(b[0]), "r"(b[1]));
}
__device__ __forceinline__ void cp16(uint32_t saddr, const void* g) {
    asm volatile("cp.async.cg.shared.global [%0], [%1], 16;" :: "r"(saddr), "l"(g));
}
#define CP_COMMIT() asm volatile("cp.async.commit_group;" ::: "memory")
template<int N> __device__ __forceinline__ void cp_wait() {
    asm volatile("cp.async.wait_group %0;" :: "n"(N) : "memory");
}

// M128 x N64 warp-tiled MMA phase (8 warps as 4m x 2n, warp tile 32x32) — gemm1
template<int AS, int NKS>
__device__ __forceinline__ void mma_m128n64(uint32_t sb, uint32_t oA, uint32_t oB,
                                            float acc[2][4][4], int wid, int lid) {
    int arow = (wid >> 1) * 32, brow = (wid & 1) * 32;
    int lr = lid & 15, lc8 = (lid >> 4) << 3;
    #pragma unroll
    for (int ks = 0; ks < NKS; ks++) {
        int k0 = ks * 16;
        uint32_t a[2][4];
        #pragma unroll
        for (int mi = 0; mi < 2; mi++) {
            uint32_t off = (uint32_t)(((arow + mi * 16 + lr) * AS + k0 + lc8) * 2);
            ldsm_x4(sb + oA + off, a[mi][0], a[mi][1], a[mi][2], a[mi][3]);
        }
        uint32_t b[4][2];
        #pragma unroll
        for (int nj = 0; nj < 2; nj++) {
            uint32_t off = (uint32_t)(((brow + nj * 16 + lr) * AS + k0 + lc8) * 2);
            uint32_t r0, r1, r2, r3;
            ldsm_x4(sb + oB + off, r0, r1, r2, r3);
            b[nj * 2][0] = r0; b[nj * 2 + 1][0] = r1;
            b[nj * 2][1] = r2; b[nj * 2 + 1][1] = r3;
        }
        #pragma unroll
        for (int mi = 0; mi < 2; mi++)
            #pragma unroll
            for (int n = 0; n < 4; n++)
                mma_f16(acc[mi][n], a[mi], b[n]);
    }
}

// M64 x N128 warp-tiled MMA phase (8 warps as 2m x 4n, warp tile 32x32)
template<int AS, int NKS>
__device__ __forceinline__ void mma_tile64(uint32_t sb, uint32_t oA, uint32_t oB,
                                           float acc[2][4][4], int wid, int lid) {
    int wm = wid >> 2, wn = wid & 3;
    int arow = wm * 32, brow = wn * 32;
    int lr = lid & 15, lc8 = (lid >> 4) << 3;
    #pragma unroll
    for (int ks = 0; ks < NKS; ks++) {
        int k0 = ks * 16;
        uint32_t a[2][4];
        #pragma unroll
        for (int mi = 0; mi < 2; mi++) {
            uint32_t off = (uint32_t)(((arow + mi * 16 + lr) * AS + k0 + lc8) * 2);
            ldsm_x4(sb + oA + off, a[mi][0], a[mi][1], a[mi][2], a[mi][3]);
        }
        uint32_t b[4][2];
        #pragma unroll
        for (int nj = 0; nj < 2; nj++) {
            uint32_t off = (uint32_t)(((brow + nj * 16 + lr) * AS + k0 + lc8) * 2);
            uint32_t r0, r1, r2, r3;
            ldsm_x4(sb + oB + off, r0, r1, r2, r3);
            b[nj * 2][0] = r0; b[nj * 2 + 1][0] = r1;
            b[nj * 2][1] = r2; b[nj * 2 + 1][1] = r3;
        }
        #pragma unroll
        for (int mi = 0; mi < 2; mi++)
            #pragma unroll
            for (int n = 0; n < 4; n++)
                mma_f16(acc[mi][n], a[mi], b[n]);
    }
}

// ---------------- K0: merged embed gather + prep -------------------------------
__global__ void embed_prep(const int* __restrict__ seq,
                           const float* __restrict__ emb,
                           const float* __restrict__ in_proj_w,
                           const float* __restrict__ in_proj_b,
                           const float* __restrict__ out_proj_w,
                           const float* __restrict__ out_proj_b,
                           const float* __restrict__ rec_emb,
                           const float* __restrict__ w1,
                           const float* __restrict__ w2) {
    int bid = blockIdx.x, tid = threadIdx.x;
    if (bid < 8192) {
        __shared__ int s_idx[2 * SEQ_L];
        int half = tid >> 7;
        int t = tid & 127;
        int b = bid * 2 + half;
        if (t < SEQ_L) s_idx[half * SEQ_L + t] = seq[b * SEQ_L + t];
        __syncthreads();
        if (t < DIM) {
            float acc = 0.f;
            #pragma unroll 5
            for (int l = 0; l < SEQ_L; l++)
                acc += emb[(size_t)s_idx[half * SEQ_L + l] * DIM + t];
            g_x[b * DIM + t] = acc;
        }
        return;
    }
    int pid = bid - 8192;
    if (pid < 64) {
        int i = pid * 2 + (tid >> 7);
        int j = tid & 127;
        const float* Wv = in_proj_w + 2 * DIM * DIM;
        const float* bv = in_proj_b + 2 * DIM;
        float mv = 0.f;
        if (i < DIM && j < DIM) {
            #pragma unroll 4
            for (int k = 0; k < DIM; k++)
                mv += out_proj_w[i * DIM + k] * Wv[k * DIM + j];
        }
        g_Mf[i * KPAD + j] = __float2half_rn(mv);
        if (j == 0) {
            float s = 0.f;
            if (i < DIM) {
                s = out_proj_b[i];
                for (int k = 0; k < DIM; k++)
                    s += out_proj_w[i * DIM + k] * bv[k];
            }
            g_c[i] = s;
        }
    } else if (pid < 128) {
        int idx = (pid - 64) * 256 + tid;
        int n = idx >> 7, k = idx & 127;
        float v = (n < DIM && k < DIM) ? rec_emb[n * DIM + k] : 0.f;
        g_recf[idx] = __float2half_rn(v);
    } else if (pid < 128 + 1024) {
        int idx = (pid - 128) * 256 + tid;
        int n = idx >> 7, k = idx & 127;
        float v = (k < DIM) ? w1[n * DIM + k] : 0.f;
        g_w1f[idx] = __float2half_rn(v);
    } else {
        int idx = (pid - 1152) * 256 + tid;
        int n = idx >> 11, k = idx & 2047;
        float v = (n < DIM) ? w2[n * FFDIM + k] : 0.f;
        g_w2f[idx] = __float2half_rn(v);
    }
}

// ---------------- M64 fused-tile smem layout (attn_ln1 / ln2_score) -----------
#define FAS 136
#define A64_SZ (64 * FAS * 2)
#define B128_SZ (128 * FAS * 2)
#define F2_A 0
#define F2_B A64_SZ
#define F2_T (A64_SZ + B128_SZ)
#define F2_SMEM (F2_T + 1024)

// ---------------- K2: fused attn + LN1 (M-tile 64, 256 CTAs) ------------------
__global__ __launch_bounds__(256, 3)
void attn_ln1_tc(const float* __restrict__ ln1_g, const float* __restrict__ ln1_b) {
    extern __shared__ char smem[];
    uint32_t sb = smem_u32(smem);
    int tid = threadIdx.x, wid = tid >> 5, lid = tid & 31;
    int m0 = blockIdx.x * 64;
    float* cvec = (float*)(smem + F2_T);
    if (tid < KPAD) cvec[tid] = g_c[tid];

    for (int idx = tid; idx < 64 * 128; idx += 256) {
        int r = idx >> 7, j = idx & 127;
        float v = (j < DIM) ? g_x[(size_t)(m0 + r) * DIM + j] : 0.f;
        *(fp16*)(smem + F2_A + ((r * FAS + j) << 1)) = __float2half_rn(v);
    }
    const uint4* B4 = (const uint4*)g_Mf;
    #pragma unroll
    for (int i = 0; i < 8; i++) {
        int idx = tid + i * 256;
        int r = idx >> 4, c = idx & 15;
        uint32_t so = (uint32_t)((r * FAS + c * 8) * 2);
        *(uint4*)(smem + F2_B + so) = B4[r * 16 + c];
    }
    __syncthreads();

    float acc[2][4][4] = {};
    mma_tile64<FAS, 8>(sb, F2_A, F2_B, acc, wid, lid);
    __syncthreads();

    float* ybuf = (float*)smem;
    int wm = wid >> 2, wn = wid & 3;
    int arow = wm * 32, brow = wn * 32;
    #pragma unroll
    for (int mi = 0; mi < 2; mi++)
        #pragma unroll
        for (int n = 0; n < 4; n++) {
            int r = arow + mi * 16 + (lid >> 2);
            int c = brow + n * 8 + (lid & 3) * 2;
            float x0 = (c     < DIM) ? g_x[(size_t)(m0 + r) * DIM + c]     : 0.f;
            float x1v= (c + 1 < DIM) ? g_x[(size_t)(m0 + r) * DIM + c + 1] : 0.f;
            float x2 = (c     < DIM) ? g_x[(size_t)(m0 + r + 8) * DIM + c]     : 0.f;
            float x3 = (c + 1 < DIM) ? g_x[(size_t)(m0 + r + 8) * DIM + c + 1] : 0.f;
            ybuf[r * 132 + c]           = acc[mi][n][0] + x0  + cvec[c];
            ybuf[r * 132 + c + 1]       = acc[mi][n][1] + x1v + cvec[c + 1];
            ybuf[(r + 8) * 132 + c]     = acc[mi][n][2] + x2  + cvec[c];
            ybuf[(r + 8) * 132 + c + 1] = acc[mi][n][3] + x3  + cvec[c + 1];
        }
    __syncthreads();

    for (int rr = 0; rr < 8; rr++) {
        int r = wid * 8 + rr;
        float v[4], s = 0.f, sq = 0.f;
        #pragma unroll
        for (int q = 0; q < 4; q++) {
            int t = lid + q * 32;
            v[q] = (t < DIM) ? ybuf[r * 132 + t] : 0.f;
            s += v[q]; sq += v[q] * v[q];
        }
        #pragma unroll
        for (int off = 16; off; off >>= 1) {
            s  += __shfl_xor_sync(0xffffffffu, s,  off);
            sq += __shfl_xor_sync(0xffffffffu, sq, off);
        }
        float m = s / DIM;
        float inv = rsqrtf(sq / DIM - m * m + EPS);
        #pragma unroll
        for (int q = 0; q < 4; q++) {
            int t = lid + q * 32;
            float o = (t < DIM) ? (v[q] - m) * inv * ln1_g[t] + ln1_b[t] : 0.f;
            g_x1 [(size_t)(m0 + r) * KPAD + t] = o;
            g_x1f[(size_t)(m0 + r) * KPAD + t] = __float2half_rn(o);
        }
    }
}

// ---------------- K3: GEMM1: tile 128x64, occ 3, cp.async 2-stage --------------
#define AS1 72
#define PA1 (128 * AS1 * 2)
#define PB1 (64 * AS1 * 2)
#define STG1 (PA1 + PB1)
#define S1_BIAS (2 * STG1)
#define G1_SMEM (2 * STG1 + 512)

__global__ __launch_bounds__(256, 3)
void gemm1_mma(const float* __restrict__ b1) {
    extern __shared__ char smem[];
    uint32_t sb = smem_u32(smem);
    int tid = threadIdx.x, wid = tid >> 5, lid = tid & 31;
    int m0 = blockIdx.x * 128, n0 = blockIdx.y * 64;
    float* bias = (float*)(smem + S1_BIAS);
    if (tid < 64) bias[tid] = b1[n0 + tid];

    const uint4* A4 = (const uint4*)g_x1f + (size_t)m0 * 16;
    const uint4* B4 = (const uint4*)g_w1f + (size_t)n0 * 16;

    auto load_stage = [&](int kh, int buf) {
        uint32_t bb = sb + buf * STG1;
        #pragma unroll
        for (int i = 0; i < 4; i++) {
            int idx = tid + i * 256;
            int r = idx >> 3, c = idx & 7;
            uint32_t so = (uint32_t)((r * AS1 + c * 8) * 2);
            cp16(bb + so, A4 + (size_t)r * 16 + kh * 8 + c);
        }
        #pragma unroll
        for (int i = 0; i < 2; i++) {
            int idx = tid + i * 256;
            int r = idx >> 3, c = idx & 7;
            uint32_t so = (uint32_t)((r * AS1 + c * 8) * 2);
            cp16(bb + PA1 + so, B4 + (size_t)r * 16 + kh * 8 + c);
        }
    };

    float acc[2][4][4] = {};
    load_stage(0, 0); CP_COMMIT();
    load_stage(1, 1); CP_COMMIT();
    cp_wait<1>();
    __syncthreads();
    mma_m128n64<AS1, 4>(sb, 0, PA1, acc, wid, lid);
    cp_wait<0>();
    __syncthreads();
    mma_m128n64<AS1, 4>(sb, STG1, STG1 + PA1, acc, wid, lid);
    __syncthreads();

    int arow = (wid >> 1) * 32, brow = (wid & 1) * 32;
    __half2* sh2 = (__half2*)smem;
    #pragma unroll
    for (int mi = 0; mi < 2; mi++)
        #pragma unroll
        for (int n = 0; n < 4; n++) {
            int r = arow + mi * 16 + (lid >> 2);
            int c = brow + n * 8 + (lid & 3) * 2;
            float v0 = fmaxf(acc[mi][n][0] + bias[c], 0.f);
            float v1 = fmaxf(acc[mi][n][1] + bias[c + 1], 0.f);
            float v2 = fmaxf(acc[mi][n][2] + bias[c], 0.f);
            float v3 = fmaxf(acc[mi][n][3] + bias[c + 1], 0.f);
            sh2[r * 36 + (c >> 1)]       = __halves2half2(__float2half_rn(v0), __float2half_rn(v1));
            sh2[(r + 8) * 36 + (c >> 1)] = __halves2half2(__float2half_rn(v2), __float2half_rn(v3));
        }
    __syncthreads();
    uint4* HF = (uint4*)g_hf;
    #pragma unroll
    for (int i = 0; i < 4; i++) {
        int idx = tid + i * 256;
        int r = idx >> 3, c = idx & 7;
        uint32_t so = (uint32_t)((r * AS1 + c * 8) * 2);
        HF[(size_t)(m0 + r) * 256 + (n0 >> 3) + c] = *(uint4*)(smem + so);
    }
}

// ---------------- K4: GEMM2: M64, K-split 4 -> 1024 CTAs, 4-stage pipeline -----
#define AS2 40
#define ST_A (64 * AS2 * 2)
#define ST_B (128 * AS2 * 2)
#define BUF2 (ST_A + ST_B)
#define G2_SMEM (4 * BUF2 + 512)

__global__ __launch_bounds__(256, 3)
void gemm2_mma() {
    extern __shared__ char smem[];
    uint32_t sb = smem_u32(smem);
    int tid = threadIdx.x, wid = tid >> 5, lid = tid & 31;
    int m0 = blockIdx.x * 64;
    int ksp = blockIdx.y;                    // 0..3, K quarter

    const uint4* srcA = (const uint4*)g_hf  + (size_t)m0 * 256 + ksp * 64;
    const uint4* srcB = (const uint4*)g_w2f + ksp * 64;
    float* dst = (ksp == 0) ? g_ff0 : (ksp == 1) ? g_ff1 : (ksp == 2) ? g_ff2 : g_ff3;

    auto load_chunk = [&](int c, int buf) {
        uint32_t bb = sb + buf * BUF2;
        {
            int r = tid >> 2, cc = tid & 3;
            uint32_t so = (uint32_t)((r * AS2 + cc * 8) * 2);
            cp16(bb + so, srcA + (size_t)r * 256 + c * 4 + cc);
        }
        #pragma unroll
        for (int i = 0; i < 2; i++) {
            int idx = tid + i * 256;
            int r = idx >> 2, cc = idx & 3;
            uint32_t so = (uint32_t)((r * AS2 + cc * 8) * 2);
            cp16(bb + ST_A + so, srcB + (size_t)r * 256 + c * 4 + cc);
        }
    };

    float acc[2][4][4] = {};
    load_chunk(0, 0); CP_COMMIT();
    load_chunk(1, 1); CP_COMMIT();
    load_chunk(2, 2); CP_COMMIT();

    for (int c = 0; c < 16; c++) {
        cp_wait<2>();
        __syncthreads();
        if (c + 3 < 16) load_chunk(c + 3, (c + 3) & 3);
        CP_COMMIT();
        uint32_t bb = sb + (c & 3) * BUF2;
        mma_tile64<AS2, 2>(bb, 0, ST_A, acc, wid, lid);
    }

    int wm = wid >> 2, wn = wid & 3;
    int arow = wm * 32, brow = wn * 32;
    #pragma unroll
    for (int mi = 0; mi < 2; mi++)
        #pragma unroll
        for (int n = 0; n < 4; n++) {
            int gr = m0 + arow + mi * 16 + (lid >> 2);
            int cc = brow + n * 8 + (lid & 3) * 2;
            if (cc < DIM) {
                dst[(size_t)gr * DIM + cc]       = acc[mi][n][0];
                dst[(size_t)(gr + 8) * DIM + cc] = acc[mi][n][2];
            }
            if (cc + 1 < DIM) {
                dst[(size_t)gr * DIM + cc + 1]       = acc[mi][n][1];
                dst[(size_t)(gr + 8) * DIM + cc + 1] = acc[mi][n][3];
            }
        }
}

// ---------------- K5: fused LN2 + scoring (M-tile 64, 256 CTAs) ----------------
__global__ __launch_bounds__(256, 3)
void ln2_score_tc(const float* __restrict__ ln2_g, const float* __restrict__ ln2_b,
                  const int* __restrict__ items, const float* __restrict__ rec_b,
                  const float* __restrict__ b2, float* __restrict__ out) {
    extern __shared__ char smem[];
    uint32_t sb = smem_u32(smem);
    int tid = threadIdx.x, wid = tid >> 5, lid = tid & 31;
    int m0 = blockIdx.x * 64;
    float* srecb = (float*)(smem + F2_T);
    float* sb2   = (float*)(smem + F2_T + 512);
    if (tid < KPAD) {
        srecb[tid] = (tid < DIM) ? rec_b[tid] : 0.f;
        sb2[tid]   = (tid < DIM) ? b2[tid]    : 0.f;
    }

    const uint4* B4 = (const uint4*)g_recf;
    #pragma unroll
    for (int i = 0; i < 8; i++) {
        int idx = tid + i * 256;
        int r = idx >> 4, c = idx & 15;
        uint32_t so = (uint32_t)((r * FAS + c * 8) * 2);
        *(uint4*)(smem + F2_B + so) = B4[r * 16 + c];
    }
    __syncthreads();

    for (int rr = 0; rr < 8; rr++) {
        int r = wid * 8 + rr;
        float v[4], s = 0.f, sq = 0.f;
        #pragma unroll
        for (int q = 0; q < 4; q++) {
            int t = lid + q * 32;
            v[q] = 0.f;
            if (t < DIM) {
                size_t o = (size_t)(m0 + r) * DIM + t;
                v[q] = g_x1[(size_t)(m0 + r) * KPAD + t]
                     + (g_ff0[o] + g_ff1[o] + g_ff2[o] + g_ff3[o] + sb2[t]);
            }
            s += v[q]; sq += v[q] * v[q];
        }
        #pragma unroll
        for (int off = 16; off; off >>= 1) {
            s  += __shfl_xor_sync(0xffffffffu, s,  off);
            sq += __shfl_xor_sync(0xffffffffu, sq, off);
        }
        float m = s / DIM;
        float inv = rsqrtf(sq / DIM - m * m + EPS);
        #pragma unroll
        for (int q = 0; q < 4; q++) {
            int t = lid + q * 32;
            float o = (t < DIM) ? (v[q] - m) * inv * ln2_g[t] + ln2_b[t] : 0.f;
            *(fp16*)(smem + F2_A + ((r * FAS + t) << 1)) = __float2half_rn(o);
        }
    }
    __syncthreads();

    float acc[2][4][4] = {};
    mma_tile64<FAS, 8>(sb, F2_A, F2_B, acc, wid, lid);
    __syncthreads();

    float* fbuf = (float*)smem;
    int wm = wid >> 2, wn = wid & 3;
    int arow = wm * 32, brow = wn * 32;
    #pragma unroll
    for (int mi = 0; mi < 2; mi++)
        #pragma unroll
        for (int n = 0; n < 4; n++) {
            int r = arow + mi * 16 + (lid >> 2);
            int c = brow + n * 8 + (lid & 3) * 2;
            fbuf[r * 128 + c]           = acc[mi][n][0];
            fbuf[r * 128 + c + 1]       = acc[mi][n][1];
            fbuf[(r + 8) * 128 + c]     = acc[mi][n][2];
            fbuf[(r + 8) * 128 + c + 1] = acc[mi][n][3];
        }
    __syncthreads();

    for (int o = tid; o < 64 * KPRED; o += 256) {
        int r = o / KPRED, k = o - r * KPRED;
        int idx = items[(size_t)(m0 + r) * KPRED + k];
        out[(size_t)(m0 + r) * KPRED + k] = fbuf[r * 128 + idx] + srecb[idx];
    }
}

// ---------------- launch ------------------------------------------------------
extern "C" void kernel_launch(void* const* d_in, const int* in_sizes, int n_in,
                              void* d_out, int out_size) {
    const int*   item_seq   = (const int*)  d_in[0];
    const int*   items_pred = (const int*)  d_in[1];
    const float* item_emb_w = (const float*)d_in[2];
    const float* rec_emb_w  = (const float*)d_in[3];
    const float* rec_b_w    = (const float*)d_in[4];
    const float* in_proj_w  = (const float*)d_in[5];
    const float* in_proj_b  = (const float*)d_in[6];
    const float* out_proj_w = (const float*)d_in[7];
    const float* out_proj_b = (const float*)d_in[8];
    const float* ln1_g      = (const float*)d_in[9];
    const float* ln1_b      = (const float*)d_in[10];
    const float* ln2_g      = (const float*)d_in[11];
    const float* ln2_b      = (const float*)d_in[12];
    const float* ffn_w1     = (const float*)d_in[13];
    const float* ffn_b1     = (const float*)d_in[14];
    const float* ffn_w2     = (const float*)d_in[15];
    const float* ffn_b2     = (const float*)d_in[16];
    float* out = (float*)d_out;

    int B = in_sizes[0] / SEQ_L;

    cudaFuncSetAttribute(attn_ln1_tc,  cudaFuncAttributeMaxDynamicSharedMemorySize, F2_SMEM);
    cudaFuncSetAttribute(ln2_score_tc, cudaFuncAttributeMaxDynamicSharedMemorySize, F2_SMEM);
    cudaFuncSetAttribute(gemm1_mma, cudaFuncAttributeMaxDynamicSharedMemorySize, G1_SMEM);
    cudaFuncSetAttribute(gemm2_mma, cudaFuncAttributeMaxDynamicSharedMemorySize, G2_SMEM);

    embed_prep<<<B / 2 + 2176, 256>>>(item_seq, item_emb_w,
                                      in_proj_w, in_proj_b, out_proj_w, out_proj_b,
                                      rec_emb_w, ffn_w1, ffn_w2);
    attn_ln1_tc<<<B / 64, 256, F2_SMEM>>>(ln1_g, ln1_b);
    gemm1_mma<<<dim3(B / 128, FFDIM / 64), 256, G1_SMEM>>>(ffn_b1);
    gemm2_mma<<<dim3(B / 64, 4), 256, G2_SMEM>>>();
    ln2_score_tc<<<B / 64, 256, F2_SMEM>>>(ln2_g, ln2_b, items_pred, rec_b_w,
                                           ffn_b2, out);
}